// round 9
// baseline (speedup 1.0000x reference)
#include <cuda_runtime.h>
#include <cuda_bf16.h>
#include <cstdint>
#include <cstddef>

#define HID   4096
#define LQ    128
#define CTXN  896
#define TT    1024
#define STATE 3072
#define HQ    32
#define HKV   8
#define DH    128
#define SCALE 0.08838834764831845f
#define NEPS  1e-6f

// ---------------- scratch (device globals; no allocation APIs) ----------------
__device__ float g_q [LQ * HID];
__device__ float g_qr[HQ * LQ * DH];
__device__ float g_k [TT * HKV * DH];
__device__ float g_v [TT * HKV * DH];
__device__ float g_o [LQ * HID];

__device__ __nv_bfloat16 c_actH[TT * HID];
__device__ __nv_bfloat16 c_actL[TT * HID];
__device__ __nv_bfloat16 c_wqH [HID * HID];
__device__ __nv_bfloat16 c_wqL [HID * HID];
__device__ __nv_bfloat16 c_wkH [HKV * DH * HID];
__device__ __nv_bfloat16 c_wkL [HKV * DH * HID];
__device__ __nv_bfloat16 c_wvH [HKV * DH * HID];
__device__ __nv_bfloat16 c_wvL [HKV * DH * HID];
__device__ __nv_bfloat16 c_woH [HID * HID];
__device__ __nv_bfloat16 c_woL [HID * HID];
__device__ __nv_bfloat16 c_goH [LQ * HID];
__device__ __nv_bfloat16 c_goL [LQ * HID];

// ---------------- packed f32x2 helpers ----------------
static __device__ __forceinline__ unsigned long long pk2(float x) {
    unsigned long long r; unsigned u = __float_as_uint(x);
    asm("mov.b64 %0, {%1, %1};" : "=l"(r) : "r"(u));
    return r;
}
static __device__ __forceinline__ void fma2(unsigned long long& c,
                                            unsigned long long a,
                                            unsigned long long b) {
    asm("fma.rn.f32x2 %0, %1, %2, %0;" : "+l"(c) : "l"(a), "l"(b));
}
static __device__ __forceinline__ unsigned long long mul2(unsigned long long a,
                                                          unsigned long long b) {
    unsigned long long d;
    asm("mul.rn.f32x2 %0, %1, %2;" : "=l"(d) : "l"(a), "l"(b));
    return d;
}
static __device__ __forceinline__ float2 up2(unsigned long long v) {
    unsigned lo, hi;
    asm("mov.b64 {%0, %1}, %2;" : "=r"(lo), "=r"(hi) : "l"(v));
    return make_float2(__uint_as_float(lo), __uint_as_float(hi));
}

// ---------------- mma helpers ----------------
static __device__ __forceinline__ uint32_t smem_u32(const void* p) {
    uint32_t a;
    asm("{ .reg .u64 t; cvta.to.shared.u64 t, %1; cvt.u32.u64 %0, t; }"
        : "=r"(a) : "l"(p));
    return a;
}
static __device__ __forceinline__ void ldm4(uint32_t* r, uint32_t addr) {
    asm volatile("ldmatrix.sync.aligned.m8n8.x4.shared.b16 {%0,%1,%2,%3}, [%4];"
                 : "=r"(r[0]), "=r"(r[1]), "=r"(r[2]), "=r"(r[3]) : "r"(addr));
}
static __device__ __forceinline__ void mma_bf16(float* c, const uint32_t* a,
                                                uint32_t b0, uint32_t b1) {
    asm volatile(
        "mma.sync.aligned.m16n8k16.row.col.f32.bf16.bf16.f32 "
        "{%0,%1,%2,%3}, {%4,%5,%6,%7}, {%8,%9}, {%0,%1,%2,%3};"
        : "+f"(c[0]), "+f"(c[1]), "+f"(c[2]), "+f"(c[3])
        : "r"(a[0]), "r"(a[1]), "r"(a[2]), "r"(a[3]), "r"(b0), "r"(b1));
}
#define CPA16(dst, src) \
    asm volatile("cp.async.cg.shared.global [%0], [%1], 16;" \
                 :: "r"(dst), "l"(src) : "memory")
#define CPA_COMMIT() asm volatile("cp.async.commit_group;" ::: "memory")
#define CPA_WAIT1()  asm volatile("cp.async.wait_group 1;" ::: "memory")

// ---------------- fp32 -> (hi, lo) split core ----------------
static __device__ __forceinline__ void split4(float4 f, uint2& h, uint2& l) {
    uint32_t u0 = __float_as_uint(f.x), u1 = __float_as_uint(f.y);
    uint32_t u2 = __float_as_uint(f.z), u3 = __float_as_uint(f.w);
    h.x = __byte_perm(u0, u1, 0x7632);
    h.y = __byte_perm(u2, u3, 0x7632);
    float l0 = f.x - __uint_as_float(u0 & 0xFFFF0000u);
    float l1 = f.y - __uint_as_float(u1 & 0xFFFF0000u);
    float l2 = f.z - __uint_as_float(u2 & 0xFFFF0000u);
    float l3 = f.w - __uint_as_float(u3 & 0xFFFF0000u);
    __nv_bfloat162 p0 = __float22bfloat162_rn(make_float2(l0, l1));
    __nv_bfloat162 p1 = __float22bfloat162_rn(make_float2(l2, l3));
    l.x = *(uint32_t*)&p0;
    l.y = *(uint32_t*)&p1;
}

// acts: concat(xctx, x) -> c_act{H,L}
#define ACT4   (TT * HID / 4)
#define CTX4   (CTXN * HID / 4)
__global__ __launch_bounds__(256) void cvt_a(
    const float4* __restrict__ xctx, const float4* __restrict__ x,
    uint2* __restrict__ hi, uint2* __restrict__ lo)
{
    int i = blockIdx.x * 256 + threadIdx.x;
    if (i >= ACT4) return;
    float4 f = (i < CTX4) ? xctx[i] : x[i - CTX4];
    uint2 h, l; split4(f, h, l);
    hi[i] = h; lo[i] = l;
}

// weights: Wq | Wk | Wv | Wo
#define WQ4 (HID * HID / 4)
#define WK4 (HKV * DH * HID / 4)
__global__ __launch_bounds__(256) void cvt_w(
    const float4* __restrict__ wq, const float4* __restrict__ wk,
    const float4* __restrict__ wv, const float4* __restrict__ wo,
    uint2* __restrict__ qH, uint2* __restrict__ qL,
    uint2* __restrict__ kH, uint2* __restrict__ kL,
    uint2* __restrict__ vH, uint2* __restrict__ vL,
    uint2* __restrict__ oH, uint2* __restrict__ oL)
{
    long long i = (long long)blockIdx.x * 256 + threadIdx.x;
    const long long s0 = WQ4, s1 = s0 + WK4, s2 = s1 + WK4, s3 = s2 + WQ4;
    if (i >= s3) return;
    const float4* src; uint2 *dh, *dl; long long j;
    if      (i < s0) { src = wq; dh = qH; dl = qL; j = i; }
    else if (i < s1) { src = wk; dh = kH; dl = kL; j = i - s0; }
    else if (i < s2) { src = wv; dh = vH; dl = vL; j = i - s1; }
    else             { src = wo; dh = oH; dl = oL; j = i - s2; }
    uint2 h, l; split4(src[j], h, l);
    dh[j] = h; dl[j] = l;
}

__global__ __launch_bounds__(256) void cvt_go(
    const float4* __restrict__ src, uint2* __restrict__ hi,
    uint2* __restrict__ lo, int n4)
{
    int i = blockIdx.x * 256 + threadIdx.x;
    if (i >= n4) return;
    uint2 h, l; split4(src[i], h, l);
    hi[i] = h; lo[i] = l;
}

// ============ GEMM: C[M,N] = A[M,4096] * B[N,4096]^T (pre-split bf16) ========
// CTA 64m x 128n, 256 thr, 8 warps (2m x 4n), warp tile 32x32.
// 3-stage cp.async; 3-term split: Ah*Bh + Al*Bh + Ah*Bl, fp32 accum.
#define GP     40
#define A_B    5120u    // 64 rows * 80 B
#define B_B    10240u   // 128 rows * 80 B
#define STG_B  30720u   // Ah | Al | Bh | Bl
__global__ __launch_bounds__(256) void gemm_bf3(
    const __nv_bfloat16* __restrict__ aH, const __nv_bfloat16* __restrict__ aL,
    const __nv_bfloat16* __restrict__ bH, const __nv_bfloat16* __restrict__ bL,
    float* __restrict__ C, int ldc)
{
    extern __shared__ __align__(16) char sm[];
    const int tid  = threadIdx.x;
    const int lane = tid & 31;
    const int wid  = tid >> 5;
    const int wm   = wid >> 2;        // 0..1
    const int wn   = wid & 3;         // 0..3
    const int m0   = blockIdx.y * 64;
    const int n0   = blockIdx.x * 128;

    const int arow = tid >> 2, ac = tid & 3;
    const __nv_bfloat16* gaH = aH + (size_t)(m0 + arow) * 4096 + ac * 8;
    const __nv_bfloat16* gaL = aL + (size_t)(m0 + arow) * 4096 + ac * 8;
    const __nv_bfloat16* gbH0 = bH + (size_t)(n0 + arow) * 4096 + ac * 8;
    const __nv_bfloat16* gbL0 = bL + (size_t)(n0 + arow) * 4096 + ac * 8;
    const __nv_bfloat16* gbH1 = gbH0 + (size_t)64 * 4096;
    const __nv_bfloat16* gbL1 = gbL0 + (size_t)64 * 4096;

    const uint32_t smBase = smem_u32(sm);
    const uint32_t aOff = (uint32_t)(arow * 80 + ac * 16);
    const uint32_t bOff0 = aOff, bOff1 = aOff + 64u * 80u;

    // ldmatrix address parts
    const int mrl = (lane & 7) + ((lane >> 3) & 1) * 8;
    const int kof = ((lane >> 4) & 1) * 8;
    const uint32_t lmA = (uint32_t)(((32 * wm + mrl) * GP + kof) * 2);
    const uint32_t lmB = (uint32_t)(((32 * wn + mrl) * GP + kof) * 2);

    float acc[2][4][4];
#pragma unroll
    for (int i = 0; i < 2; i++)
#pragma unroll
        for (int j = 0; j < 4; j++)
#pragma unroll
            for (int e = 0; e < 4; e++) acc[i][j][e] = 0.0f;

    // prologue: stages 0,1
#pragma unroll
    for (int p = 0; p < 2; p++) {
        uint32_t d = smBase + (uint32_t)p * STG_B;
        int k0 = p * 32;
        CPA16(d + aOff,              gaH  + k0);
        CPA16(d + A_B + aOff,        gaL  + k0);
        CPA16(d + 2 * A_B + bOff0,   gbH0 + k0);
        CPA16(d + 2 * A_B + bOff1,   gbH1 + k0);
        CPA16(d + 2 * A_B + B_B + bOff0, gbL0 + k0);
        CPA16(d + 2 * A_B + B_B + bOff1, gbL1 + k0);
        CPA_COMMIT();
    }

    const int NK = 128;
    int sIdx = 0;   // stage being consumed this iteration
    int fIdx = 2;   // stage being filled this iteration ( = (sIdx+2) mod 3 )
    for (int ic = 0; ic < NK; ic++) {
        CPA_WAIT1();
        __syncthreads();

        const uint32_t sb = smBase + (uint32_t)sIdx * STG_B;
#pragma unroll
        for (int ks = 0; ks < 2; ks++) {
            const uint32_t kb = (uint32_t)ks * 32;
            uint32_t Ah[2][4], Al[2][4], Bh[2][4], Bl[2][4];
            ldm4(Ah[0], sb + lmA + kb);
            ldm4(Ah[1], sb + lmA + 16 * GP * 2 + kb);
            ldm4(Al[0], sb + A_B + lmA + kb);
            ldm4(Al[1], sb + A_B + lmA + 16 * GP * 2 + kb);
            ldm4(Bh[0], sb + 2 * A_B + lmB + kb);
            ldm4(Bh[1], sb + 2 * A_B + lmB + 16 * GP * 2 + kb);
            ldm4(Bl[0], sb + 2 * A_B + B_B + lmB + kb);
            ldm4(Bl[1], sb + 2 * A_B + B_B + lmB + 16 * GP * 2 + kb);
#pragma unroll
            for (int tm = 0; tm < 2; tm++)
#pragma unroll
                for (int tn = 0; tn < 4; tn++) {
                    uint32_t bh0 = Bh[tn >> 1][tn & 1];
                    uint32_t bh1 = Bh[tn >> 1][(tn & 1) + 2];
                    uint32_t bl0 = Bl[tn >> 1][tn & 1];
                    uint32_t bl1 = Bl[tn >> 1][(tn & 1) + 2];
                    mma_bf16(acc[tm][tn], Ah[tm], bh0, bh1);
                    mma_bf16(acc[tm][tn], Al[tm], bh0, bh1);
                    mma_bf16(acc[tm][tn], Ah[tm], bl0, bl1);
                }
        }

        if (ic + 2 < NK) {
            int k0 = (ic + 2) * 32;
            uint32_t d = smBase + (uint32_t)fIdx * STG_B;
            CPA16(d + aOff,              gaH  + k0);
            CPA16(d + A_B + aOff,        gaL  + k0);
            CPA16(d + 2 * A_B + bOff0,   gbH0 + k0);
            CPA16(d + 2 * A_B + bOff1,   gbH1 + k0);
            CPA16(d + 2 * A_B + B_B + bOff0, gbL0 + k0);
            CPA16(d + 2 * A_B + B_B + bOff1, gbL1 + k0);
        }
        CPA_COMMIT();
        sIdx = (sIdx + 1 == 3) ? 0 : sIdx + 1;
        fIdx = (fIdx + 1 == 3) ? 0 : fIdx + 1;
    }

    // epilogue
    const int r0 = m0 + 32 * wm + (lane >> 2);
    const int c0 = n0 + 32 * wn + (lane & 3) * 2;
#pragma unroll
    for (int tm = 0; tm < 2; tm++)
#pragma unroll
        for (int tn = 0; tn < 4; tn++) {
            float* p = C + (size_t)(r0 + 16 * tm) * ldc + c0 + 8 * tn;
            *(float2*)p = make_float2(acc[tm][tn][0], acc[tm][tn][1]);
            float* p2 = p + (size_t)8 * ldc;
            *(float2*)p2 = make_float2(acc[tm][tn][2], acc[tm][tn][3]);
        }
}

// ---------------- ane-norm + RoPE + scale for Q ----------------
__global__ __launch_bounds__(128) void qnorm_k(
    const float* __restrict__ cq, const float* __restrict__ sq,
    const float* __restrict__ w)
{
    int h = blockIdx.x, l = blockIdx.y, d = threadIdx.x;
    __shared__ float red[8];
    __shared__ float xs[128];
    float v = g_q[l * HID + h * DH + d];
    float s1 = v, s2 = v * v;
#pragma unroll
    for (int off = 16; off; off >>= 1) {
        s1 += __shfl_down_sync(0xffffffffu, s1, off);
        s2 += __shfl_down_sync(0xffffffffu, s2, off);
    }
    if ((d & 31) == 0) { red[d >> 5] = s1; red[4 + (d >> 5)] = s2; }
    __syncthreads();
    float sum = red[0] + red[1] + red[2] + red[3];
    float sqs = red[4] + red[5] + red[6] + red[7];
    float mean = sum * (1.0f / 128.0f);
    float var  = sqs * (1.0f / 128.0f) - mean * mean;
    float xn = (v - mean) * rsqrtf(var + NEPS) * w[d];
    xs[d] = xn;
    __syncthreads();
    float rot = (d < 64) ? -xs[d + 64] : xs[d - 64];
    g_qr[((size_t)h * LQ + l) * DH + d] =
        (xn * cq[l * DH + d] + rot * sq[l * DH + d]) * SCALE;
}

// ---------------- ane-norm + RoPE for K, transpose K/V -> [HKV][T][D] ----------------
__global__ __launch_bounds__(128) void kvnorm_k(
    const float* __restrict__ ck, const float* __restrict__ sk,
    const float* __restrict__ w,
    float* __restrict__ kOut, float* __restrict__ vOut)
{
    int h = blockIdx.x, t = blockIdx.y, d = threadIdx.x;
    __shared__ float red[8];
    __shared__ float xs[128];
    float v = g_k[t * (HKV * DH) + h * DH + d];
    float s1 = v, s2 = v * v;
#pragma unroll
    for (int off = 16; off; off >>= 1) {
        s1 += __shfl_down_sync(0xffffffffu, s1, off);
        s2 += __shfl_down_sync(0xffffffffu, s2, off);
    }
    if ((d & 31) == 0) { red[d >> 5] = s1; red[4 + (d >> 5)] = s2; }
    __syncthreads();
    float sum = red[0] + red[1] + red[2] + red[3];
    float sqs = red[4] + red[5] + red[6] + red[7];
    float mean = sum * (1.0f / 128.0f);
    float var  = sqs * (1.0f / 128.0f) - mean * mean;
    float xn = (v - mean) * rsqrtf(var + NEPS) * w[d];
    xs[d] = xn;
    __syncthreads();
    float rot = (d < 64) ? -xs[d + 64] : xs[d - 64];
    kOut[((size_t)h * TT + t) * DH + d] = xn * ck[t * DH + d] + rot * sk[t * DH + d];
    vOut[((size_t)h * TT + t) * DH + d] = g_v[t * (HKV * DH) + h * DH + d];
}

// ---------------- Flash attention (fp32, f32x2 inner loops) ----------------
static __device__ __forceinline__ int swf(int r, int f) {  // f even
    return ((((f >> 2) + r) & 31) << 2) | (f & 3);
}
__global__ __launch_bounds__(256) void attn_k(
    const float* __restrict__ cK, const float* __restrict__ cV,
    const float* __restrict__ kN, const float* __restrict__ vN)
{
    const int h = blockIdx.x, qt = blockIdx.y;
    const int g = h >> 2, l0 = qt * 32, tid = threadIdx.x;

    __shared__ float sQ [32][132];
    __shared__ float sKV[32][128];
    __shared__ float sS [32][33];
    __shared__ float sM[32], sL[32], sC[32];

    for (int idx = tid; idx < 32 * 32; idx += 256) {
        int r = idx >> 5, c4 = idx & 31;
        *(float4*)&sQ[r][c4 * 4] =
            *(const float4*)&g_qr[((size_t)h * LQ + l0 + r) * DH + c4 * 4];
    }
    if (tid < 32) { sM[tid] = -1e30f; sL[tid] = 0.0f; }

    const int ldr = tid >> 3, ldf = tid & 7;
    const int ty  = tid >> 4, tx  = tid & 15;
    const int pr  = tid >> 4, pd  = tid & 15;

    unsigned long long acc[2][4];
#pragma unroll
    for (int i = 0; i < 2; i++)
#pragma unroll
        for (int j = 0; j < 4; j++) acc[i][j] = 0ULL;

    int ntile = ((STATE + CTXN + l0 + 31) >> 5) + 1;
    if (ntile > 128) ntile = 128;

    for (int st = 0; st < ntile; st++) {
        const int s0 = st * 32;
        __syncthreads();
        {
            int s = s0 + ldr;
            const float* p = (s < STATE)
                ? cK + ((size_t)(g * STATE + s)) * DH
                : kN + ((size_t)(g * TT + (s - STATE))) * DH;
#pragma unroll
            for (int i = 0; i < 4; i++) {
                int c4 = ldf + 8 * i;
                float4 v = *(const float4*)(p + c4 * 4);
                *(float4*)&sKV[ldr][((c4 + ldr) & 31) * 4] = v;
            }
        }
        __syncthreads();

        unsigned long long s00 = 0, s01 = 0, s10 = 0, s11 = 0;
#pragma unroll 8
        for (int d2 = 0; d2 < 64; d2++) {
            int f = 2 * d2;
            unsigned long long qa = *(const unsigned long long*)&sQ[ty][f];
            unsigned long long qb = *(const unsigned long long*)&sQ[ty + 16][f];
            unsigned long long ka = *(const unsigned long long*)&sKV[tx][swf(tx, f)];
            unsigned long long kb = *(const unsigned long long*)&sKV[tx + 16][swf(tx + 16, f)];
            fma2(s00, qa, ka); fma2(s01, qa, kb);
            fma2(s10, qb, ka); fma2(s11, qb, kb);
        }
        {
            float2 p00 = up2(s00), p01 = up2(s01), p10 = up2(s10), p11 = up2(s11);
            int lA = l0 + ty, lB = lA + 16, cA = s0 + tx, cB = cA + 16;
            sS[ty][tx]           = (cA <= 3968 + lA) ? p00.x + p00.y : -1e30f;
            sS[ty][tx + 16]      = (cB <= 3968 + lA) ? p01.x + p01.y : -1e30f;
            sS[ty + 16][tx]      = (cA <= 3968 + lB) ? p10.x + p10.y : -1e30f;
            sS[ty + 16][tx + 16] = (cB <= 3968 + lB) ? p11.x + p11.y : -1e30f;
        }
        __syncthreads();

        float4 vreg[4];
        {
            int s = s0 + ldr;
            const float* p = (s < STATE)
                ? cV + ((size_t)(g * STATE + s)) * DH
                : vN + ((size_t)(g * TT + (s - STATE))) * DH;
#pragma unroll
            for (int i = 0; i < 4; i++)
                vreg[i] = *(const float4*)(p + (ldf + 8 * i) * 4);
        }
        if (tid < 32) {
            int r = tid;
            float m = sM[r], mx = m;
            float sv[32];
#pragma unroll
            for (int j = 0; j < 32; j++) { sv[j] = sS[r][j]; mx = fmaxf(mx, sv[j]); }
            float c = __expf(m - mx), sum = 0.0f;
#pragma unroll
            for (int j = 0; j < 32; j++) { float e = __expf(sv[j] - mx); sS[r][j] = e; sum += e; }
            sM[r] = mx; sL[r] = sL[r] * c + sum; sC[r] = c;
        }
#pragma unroll
        for (int i = 0; i < 4; i++) {
            int c4 = ldf + 8 * i;
            *(float4*)&sKV[ldr][((c4 + ldr) & 31) * 4] = vreg[i];
        }
        __syncthreads();

        {
            unsigned long long c0 = pk2(sC[pr]), c1 = pk2(sC[pr + 16]);
#pragma unroll
            for (int j = 0; j < 4; j++) {
                acc[0][j] = mul2(acc[0][j], c0);
                acc[1][j] = mul2(acc[1][j], c1);
            }
        }
#pragma unroll 4
        for (int kk = 0; kk < 32; kk++) {
            unsigned long long p0 = pk2(sS[pr][kk]);
            unsigned long long p1 = pk2(sS[pr + 16][kk]);
#pragma unroll
            for (int j = 0; j < 4; j++) {
                int f = 2 * pd + 32 * j;
                unsigned long long vv =
                    *(const unsigned long long*)&sKV[kk][swf(kk, f)];
                fma2(acc[0][j], p0, vv);
                fma2(acc[1][j], p1, vv);
            }
        }
    }

    float i0 = 1.0f / sL[pr], i1 = 1.0f / sL[pr + 16];
#pragma unroll
    for (int j = 0; j < 4; j++) {
        int f = 2 * pd + 32 * j;
        float2 a = up2(acc[0][j]);
        float2 b = up2(acc[1][j]);
        a.x *= i0; a.y *= i0; b.x *= i1; b.y *= i1;
        *(float2*)&g_o[(size_t)(l0 + pr) * HID + h * DH + f] = a;
        *(float2*)&g_o[(size_t)(l0 + pr + 16) * HID + h * DH + f] = b;
    }
}

// ---------------- launch ----------------
extern "C" void kernel_launch(void* const* d_in, const int* in_sizes, int n_in,
                              void* d_out, int out_size) {
    const float* x     = (const float*)d_in[0];
    const float* xctx  = (const float*)d_in[1];
    const float* cosq  = (const float*)d_in[2];
    const float* sinq  = (const float*)d_in[3];
    const float* cosk  = (const float*)d_in[4];
    const float* sink  = (const float*)d_in[5];
    const float* cK    = (const float*)d_in[6];
    const float* cV    = (const float*)d_in[7];
    const float* Wq    = (const float*)d_in[9];
    const float* Wk    = (const float*)d_in[10];
    const float* Wv    = (const float*)d_in[11];
    const float* Wo    = (const float*)d_in[12];
    const float* qw    = (const float*)d_in[13];
    const float* kw    = (const float*)d_in[14];

    float* out  = (float*)d_out;
    float* kOut = out + (size_t)LQ * HID;
    float* vOut = kOut + (size_t)HKV * TT * DH;

    cudaFuncSetAttribute(gemm_bf3, cudaFuncAttributeMaxDynamicSharedMemorySize,
                         92160);

    __nv_bfloat16 *actH, *actL, *wqH, *wqL, *wkH, *wkL, *wvH, *wvL,
                  *woH, *woL, *goH, *goL;
    cudaGetSymbolAddress((void**)&actH, c_actH);
    cudaGetSymbolAddress((void**)&actL, c_actL);
    cudaGetSymbolAddress((void**)&wqH,  c_wqH);
    cudaGetSymbolAddress((void**)&wqL,  c_wqL);
    cudaGetSymbolAddress((void**)&wkH,  c_wkH);
    cudaGetSymbolAddress((void**)&wkL,  c_wkL);
    cudaGetSymbolAddress((void**)&wvH,  c_wvH);
    cudaGetSymbolAddress((void**)&wvL,  c_wvL);
    cudaGetSymbolAddress((void**)&woH,  c_woH);
    cudaGetSymbolAddress((void**)&woL,  c_woL);
    cudaGetSymbolAddress((void**)&goH,  c_goH);
    cudaGetSymbolAddress((void**)&goL,  c_goL);
    float *gq, *gk, *gv, *go;
    cudaGetSymbolAddress((void**)&gq,  g_q);
    cudaGetSymbolAddress((void**)&gk,  g_k);
    cudaGetSymbolAddress((void**)&gv,  g_v);
    cudaGetSymbolAddress((void**)&go,  g_o);

    // #0 act conversion, #1 weight conversion
    cvt_a<<<(ACT4 + 255) / 256, 256>>>((const float4*)xctx, (const float4*)x,
                                       (uint2*)actH, (uint2*)actL);
    {
        long long tot = 2LL * WQ4 + 2LL * WK4;
        cvt_w<<<(unsigned)((tot + 255) / 256), 256>>>(
            (const float4*)Wq, (const float4*)Wk, (const float4*)Wv,
            (const float4*)Wo,
            (uint2*)wqH, (uint2*)wqL, (uint2*)wkH, (uint2*)wkL,
            (uint2*)wvH, (uint2*)wvL, (uint2*)woH, (uint2*)woL);
    }
    // #2 q projection (M=128): grid (N/128=32, M/64=2)
    gemm_bf3<<<dim3(32, 2), 256, 92160>>>(
        actH + (size_t)CTXN * HID, actL + (size_t)CTXN * HID, wqH, wqL, gq, HID);
    // #3 qnorm
    qnorm_k<<<dim3(HQ, LQ), 128>>>(cosq, sinq, qw);
    // #4 k projection, #5 v projection (profiled)
    gemm_bf3<<<dim3(8, 16), 256, 92160>>>(actH, actL, wkH, wkL, gk, HKV * DH);
    gemm_bf3<<<dim3(8, 16), 256, 92160>>>(actH, actL, wvH, wvL, gv, HKV * DH);
    // #6 kvnorm
    kvnorm_k<<<dim3(HKV, TT), 128>>>(cosk, sink, kw, kOut, vOut);
    // #7 attention
    attn_k<<<dim3(HQ, 4), 256>>>(cK, cV, kOut, vOut);
    // #8 o conversion, #9 output projection
    cvt_go<<<(LQ * HID / 4 + 255) / 256, 256>>>((const float4*)go,
                                                (uint2*)goH, (uint2*)goL,
                                                LQ * HID / 4);
    gemm_bf3<<<dim3(32, 2), 256, 92160>>>(goH, goL, woH, woL, out, HID);
}

// round 13
// speedup vs baseline: 1.8038x; 1.8038x over previous
#include <cuda_runtime.h>
#include <cuda_bf16.h>
#include <cstdint>
#include <cstddef>

#define HID   4096
#define LQ    128
#define CTXN  896
#define TT    1024
#define STATE 3072
#define HQ    32
#define HKV   8
#define DH    128
#define SCALE 0.08838834764831845f
#define NEPS  1e-6f

// ---------------- scratch (device globals; no allocation APIs) ----------------
__device__ __align__(16) float g_q [LQ * HID];
__device__ __align__(16) float g_k [TT * HKV * DH];
__device__ __align__(16) float g_v [TT * HKV * DH];
__device__ __align__(16) float g_o [LQ * HID];

__device__ __align__(16) __nv_bfloat16 c_actH[TT * HID];
__device__ __align__(16) __nv_bfloat16 c_actL[TT * HID];
__device__ __align__(16) __nv_bfloat16 c_wqH [HID * HID];
__device__ __align__(16) __nv_bfloat16 c_wqL [HID * HID];
__device__ __align__(16) __nv_bfloat16 c_wkH [HKV * DH * HID];
__device__ __align__(16) __nv_bfloat16 c_wkL [HKV * DH * HID];
__device__ __align__(16) __nv_bfloat16 c_wvH [HKV * DH * HID];
__device__ __align__(16) __nv_bfloat16 c_wvL [HKV * DH * HID];
__device__ __align__(16) __nv_bfloat16 c_woH [HID * HID];
__device__ __align__(16) __nv_bfloat16 c_woL [HID * HID];
__device__ __align__(16) __nv_bfloat16 c_goH [LQ * HID];
__device__ __align__(16) __nv_bfloat16 c_goL [LQ * HID];

// attention operands, pre-split
__device__ __align__(16) __nv_bfloat16 c_qrH[HQ * LQ * DH];
__device__ __align__(16) __nv_bfloat16 c_qrL[HQ * LQ * DH];
__device__ __align__(16) __nv_bfloat16 c_kcH[HKV * 4096 * DH];
__device__ __align__(16) __nv_bfloat16 c_kcL[HKV * 4096 * DH];
__device__ __align__(16) __nv_bfloat16 c_vcH[HKV * 4096 * DH];
__device__ __align__(16) __nv_bfloat16 c_vcL[HKV * 4096 * DH];

// ---------------- mma helpers ----------------
static __device__ __forceinline__ uint32_t smem_u32(const void* p) {
    uint32_t a;
    asm("{ .reg .u64 t; cvta.to.shared.u64 t, %1; cvt.u32.u64 %0, t; }"
        : "=r"(a) : "l"(p));
    return a;
}
static __device__ __forceinline__ void ldm4(uint32_t* r, uint32_t addr) {
    asm volatile("ldmatrix.sync.aligned.m8n8.x4.shared.b16 {%0,%1,%2,%3}, [%4];"
                 : "=r"(r[0]), "=r"(r[1]), "=r"(r[2]), "=r"(r[3]) : "r"(addr));
}
static __device__ __forceinline__ void ldm4t(uint32_t* r, uint32_t addr) {
    asm volatile("ldmatrix.sync.aligned.m8n8.x4.trans.shared.b16 {%0,%1,%2,%3}, [%4];"
                 : "=r"(r[0]), "=r"(r[1]), "=r"(r[2]), "=r"(r[3]) : "r"(addr));
}
static __device__ __forceinline__ void mma_bf16(float* c, const uint32_t* a,
                                                uint32_t b0, uint32_t b1) {
    asm volatile(
        "mma.sync.aligned.m16n8k16.row.col.f32.bf16.bf16.f32 "
        "{%0,%1,%2,%3}, {%4,%5,%6,%7}, {%8,%9}, {%0,%1,%2,%3};"
        : "+f"(c[0]), "+f"(c[1]), "+f"(c[2]), "+f"(c[3])
        : "r"(a[0]), "r"(a[1]), "r"(a[2]), "r"(a[3]), "r"(b0), "r"(b1));
}
#define CPA16(dst, src) \
    asm volatile("cp.async.cg.shared.global [%0], [%1], 16;" \
                 :: "r"(dst), "l"(src) : "memory")
#define CPA_COMMIT() asm volatile("cp.async.commit_group;" ::: "memory")
#define CPA_WAIT2()  asm volatile("cp.async.wait_group 2;" ::: "memory")
#define CPA_WAIT1G() asm volatile("cp.async.wait_group 1;" ::: "memory")

// ---------------- fp32 -> (hi, lo) split core ----------------
static __device__ __forceinline__ void split4(float4 f, uint2& h, uint2& l) {
    uint32_t u0 = __float_as_uint(f.x), u1 = __float_as_uint(f.y);
    uint32_t u2 = __float_as_uint(f.z), u3 = __float_as_uint(f.w);
    h.x = __byte_perm(u0, u1, 0x7632);
    h.y = __byte_perm(u2, u3, 0x7632);
    float l0 = f.x - __uint_as_float(u0 & 0xFFFF0000u);
    float l1 = f.y - __uint_as_float(u1 & 0xFFFF0000u);
    float l2 = f.z - __uint_as_float(u2 & 0xFFFF0000u);
    float l3 = f.w - __uint_as_float(u3 & 0xFFFF0000u);
    __nv_bfloat162 p0 = __float22bfloat162_rn(make_float2(l0, l1));
    __nv_bfloat162 p1 = __float22bfloat162_rn(make_float2(l2, l3));
    l.x = *(uint32_t*)&p0;
    l.y = *(uint32_t*)&p1;
}

// acts: concat(xctx, x) -> c_act{H,L}
#define ACT4   (TT * HID / 4)
#define CTX4   (CTXN * HID / 4)
__global__ __launch_bounds__(256) void cvt_a(
    const float4* __restrict__ xctx, const float4* __restrict__ x,
    uint2* __restrict__ hi, uint2* __restrict__ lo)
{
    int i = blockIdx.x * 256 + threadIdx.x;
    if (i >= ACT4) return;
    float4 f = (i < CTX4) ? xctx[i] : x[i - CTX4];
    uint2 h, l; split4(f, h, l);
    hi[i] = h; lo[i] = l;
}

// weights: Wq | Wk | Wv | Wo
#define WQ4 (HID * HID / 4)
#define WK4 (HKV * DH * HID / 4)
__global__ __launch_bounds__(256) void cvt_w(
    const float4* __restrict__ wq, const float4* __restrict__ wk,
    const float4* __restrict__ wv, const float4* __restrict__ wo,
    uint2* __restrict__ qH, uint2* __restrict__ qL,
    uint2* __restrict__ kH, uint2* __restrict__ kL,
    uint2* __restrict__ vH, uint2* __restrict__ vL,
    uint2* __restrict__ oH, uint2* __restrict__ oL)
{
    long long i = (long long)blockIdx.x * 256 + threadIdx.x;
    const long long s0 = WQ4, s1 = s0 + WK4, s2 = s1 + WK4, s3 = s2 + WQ4;
    if (i >= s3) return;
    const float4* src; uint2 *dh, *dl; long long j;
    if      (i < s0) { src = wq; dh = qH; dl = qL; j = i; }
    else if (i < s1) { src = wk; dh = kH; dl = kL; j = i - s0; }
    else if (i < s2) { src = wv; dh = vH; dl = vL; j = i - s1; }
    else             { src = wo; dh = oH; dl = oL; j = i - s2; }
    uint2 h, l; split4(src[j], h, l);
    dh[j] = h; dl[j] = l;
}

__global__ __launch_bounds__(256) void cvt_go(
    const float4* __restrict__ src, uint2* __restrict__ hi,
    uint2* __restrict__ lo, int n4)
{
    int i = blockIdx.x * 256 + threadIdx.x;
    if (i >= n4) return;
    uint2 h, l; split4(src[i], h, l);
    hi[i] = h; lo[i] = l;
}

// cache region of kcat/vcat: split cK/cV (s < 3072) into bf16 hi/lo
#define CCH4 (HKV * STATE * DH / 4)
__global__ __launch_bounds__(256) void cache_split(
    const float4* __restrict__ cK, const float4* __restrict__ cV,
    uint2* __restrict__ kH, uint2* __restrict__ kL,
    uint2* __restrict__ vH, uint2* __restrict__ vL)
{
    int i = blockIdx.x * 256 + threadIdx.x;
    if (i >= 2 * CCH4) return;
    const float4* src = (i < CCH4) ? cK : cV;
    uint2 *dh = (i < CCH4) ? kH : vH;
    uint2 *dl = (i < CCH4) ? kL : vL;
    int j = (i < CCH4) ? i : i - CCH4;
    int e = j * 4;
    int g = e / (STATE * DH);
    int rem = e - g * (STATE * DH);
    int s = rem / DH;
    int d = rem - s * DH;
    uint2 h, l; split4(src[j], h, l);
    size_t dst = ((size_t)(g * 4096 + s) * DH + d) / 4;
    dh[dst] = h; dl[dst] = l;
}

// ============ GEMM (R5 config): C[M,N] = A[M,4096] * B[N,4096]^T ============
#define GP       40
#define ARR_B    5120u
#define STG_B    20480u
__global__ __launch_bounds__(256) void gemm_bf3(
    const __nv_bfloat16* __restrict__ aH, const __nv_bfloat16* __restrict__ aL,
    const __nv_bfloat16* __restrict__ bH0, const __nv_bfloat16* __restrict__ bL0,
    const __nv_bfloat16* __restrict__ bH1, const __nv_bfloat16* __restrict__ bL1,
    float* __restrict__ C0, float* __restrict__ C1, int ldc)
{
    extern __shared__ __align__(16) char sm[];
    const int tid  = threadIdx.x;
    const int lane = tid & 31;
    const int wid  = tid >> 5;
    const int wm   = wid >> 2;
    const int wn   = wid & 3;
    const int m0   = blockIdx.y * 64;
    const int n0   = blockIdx.x * 64;
    const int z    = blockIdx.z;

    const __nv_bfloat16* bH = z ? bH1 : bH0;
    const __nv_bfloat16* bL = z ? bL1 : bL0;
    float* C = z ? C1 : C0;

    const int row = tid >> 2, c4 = tid & 3;
    const __nv_bfloat16* gaH = aH + (size_t)(m0 + row) * 4096 + c4 * 8;
    const __nv_bfloat16* gaL = aL + (size_t)(m0 + row) * 4096 + c4 * 8;
    const __nv_bfloat16* gbH = bH + (size_t)(n0 + row) * 4096 + c4 * 8;
    const __nv_bfloat16* gbL = bL + (size_t)(n0 + row) * 4096 + c4 * 8;

    const uint32_t smBase = smem_u32(sm);
    const uint32_t sOff   = (uint32_t)(row * 80 + c4 * 16);

    const int mrl = (lane & 7) + ((lane >> 3) & 1) * 8;
    const int kof = ((lane >> 4) & 1) * 8;
    const uint32_t aoff = (uint32_t)(((32 * wm + mrl) * GP + kof) * 2);
    const uint32_t boff = (uint32_t)(((16 * wn + mrl) * GP + kof) * 2);

    float acc[2][2][4];
#pragma unroll
    for (int i = 0; i < 2; i++)
#pragma unroll
        for (int j = 0; j < 2; j++)
#pragma unroll
            for (int e = 0; e < 4; e++) acc[i][j][e] = 0.0f;

#pragma unroll
    for (int p = 0; p < 3; p++) {
        uint32_t d = smBase + (uint32_t)p * STG_B + sOff;
        int k0 = p * 32;
        CPA16(d,             gaH + k0);
        CPA16(d + ARR_B,     gaL + k0);
        CPA16(d + 2 * ARR_B, gbH + k0);
        CPA16(d + 3 * ARR_B, gbL + k0);
        CPA_COMMIT();
    }

    const int NK = 128;
    for (int ic = 0; ic < NK; ic++) {
        CPA_WAIT2();
        __syncthreads();

        const uint32_t sb = smBase + (uint32_t)(ic & 3) * STG_B;
#pragma unroll
        for (int ks = 0; ks < 2; ks++) {
            const uint32_t kb = (uint32_t)ks * 32;
            uint32_t Ah[2][4], Al[2][4], Bh[4], Bl[4];
            ldm4(Ah[0], sb + aoff + kb);
            ldm4(Ah[1], sb + aoff + 16 * GP * 2 + kb);
            ldm4(Al[0], sb + ARR_B + aoff + kb);
            ldm4(Al[1], sb + ARR_B + aoff + 16 * GP * 2 + kb);
            ldm4(Bh,    sb + 2 * ARR_B + boff + kb);
            ldm4(Bl,    sb + 3 * ARR_B + boff + kb);
#pragma unroll
            for (int tm = 0; tm < 2; tm++)
#pragma unroll
                for (int tn = 0; tn < 2; tn++) {
                    mma_bf16(acc[tm][tn], Ah[tm], Bh[tn], Bh[tn + 2]);
                    mma_bf16(acc[tm][tn], Al[tm], Bh[tn], Bh[tn + 2]);
                    mma_bf16(acc[tm][tn], Ah[tm], Bl[tn], Bl[tn + 2]);
                }
        }

        if (ic + 3 < NK) {
            int k0 = (ic + 3) * 32;
            uint32_t d = smBase + (uint32_t)((ic + 3) & 3) * STG_B + sOff;
            CPA16(d,             gaH + k0);
            CPA16(d + ARR_B,     gaL + k0);
            CPA16(d + 2 * ARR_B, gbH + k0);
            CPA16(d + 3 * ARR_B, gbL + k0);
        }
        CPA_COMMIT();
    }

    const int r0 = m0 + 32 * wm + (lane >> 2);
    const int c0 = n0 + 16 * wn + (lane & 3) * 2;
#pragma unroll
    for (int tm = 0; tm < 2; tm++)
#pragma unroll
        for (int tn = 0; tn < 2; tn++) {
            float* p = C + (size_t)(r0 + 16 * tm) * ldc + c0 + 8 * tn;
            *(float2*)p = make_float2(acc[tm][tn][0], acc[tm][tn][1]);
            float* p2 = p + (size_t)8 * ldc;
            *(float2*)p2 = make_float2(acc[tm][tn][2], acc[tm][tn][3]);
        }
}

// ---------------- ane-norm + RoPE + scale for Q -> split bf16 ----------------
__global__ __launch_bounds__(128) void qnorm_k(
    const float* __restrict__ cq, const float* __restrict__ sq,
    const float* __restrict__ w,
    unsigned short* __restrict__ qrH, __nv_bfloat16* __restrict__ qrL)
{
    int h = blockIdx.x, l = blockIdx.y, d = threadIdx.x;
    __shared__ float red[8];
    __shared__ float xs[128];
    float v = g_q[l * HID + h * DH + d];
    float s1 = v, s2 = v * v;
#pragma unroll
    for (int off = 16; off; off >>= 1) {
        s1 += __shfl_down_sync(0xffffffffu, s1, off);
        s2 += __shfl_down_sync(0xffffffffu, s2, off);
    }
    if ((d & 31) == 0) { red[d >> 5] = s1; red[4 + (d >> 5)] = s2; }
    __syncthreads();
    float sum = red[0] + red[1] + red[2] + red[3];
    float sqs = red[4] + red[5] + red[6] + red[7];
    float mean = sum * (1.0f / 128.0f);
    float var  = sqs * (1.0f / 128.0f) - mean * mean;
    float xn = (v - mean) * rsqrtf(var + NEPS) * w[d];
    xs[d] = xn;
    __syncthreads();
    float rot = (d < 64) ? -xs[d + 64] : xs[d - 64];
    float o = (xn * cq[l * DH + d] + rot * sq[l * DH + d]) * SCALE;
    size_t idx = ((size_t)h * LQ + l) * DH + d;
    uint32_t u = __float_as_uint(o);
    qrH[idx] = (unsigned short)(u >> 16);
    qrL[idx] = __float2bfloat16_rn(o - __uint_as_float(u & 0xFFFF0000u));
}

// ---------- ane-norm + RoPE for K; outputs fp32 k/v + split kcat/vcat --------
__global__ __launch_bounds__(128) void kvnorm_k(
    const float* __restrict__ ck, const float* __restrict__ sk,
    const float* __restrict__ w,
    float* __restrict__ kOut, float* __restrict__ vOut,
    unsigned short* __restrict__ kcH, __nv_bfloat16* __restrict__ kcL,
    unsigned short* __restrict__ vcH, __nv_bfloat16* __restrict__ vcL)
{
    int h = blockIdx.x, t = blockIdx.y, d = threadIdx.x;
    __shared__ float red[8];
    __shared__ float xs[128];
    float v = g_k[t * (HKV * DH) + h * DH + d];
    float s1 = v, s2 = v * v;
#pragma unroll
    for (int off = 16; off; off >>= 1) {
        s1 += __shfl_down_sync(0xffffffffu, s1, off);
        s2 += __shfl_down_sync(0xffffffffu, s2, off);
    }
    if ((d & 31) == 0) { red[d >> 5] = s1; red[4 + (d >> 5)] = s2; }
    __syncthreads();
    float sum = red[0] + red[1] + red[2] + red[3];
    float sqs = red[4] + red[5] + red[6] + red[7];
    float mean = sum * (1.0f / 128.0f);
    float var  = sqs * (1.0f / 128.0f) - mean * mean;
    float xn = (v - mean) * rsqrtf(var + NEPS) * w[d];
    xs[d] = xn;
    __syncthreads();
    float rot = (d < 64) ? -xs[d + 64] : xs[d - 64];
    float kv = xn * ck[t * DH + d] + rot * sk[t * DH + d];
    float vv = g_v[t * (HKV * DH) + h * DH + d];
    kOut[((size_t)h * TT + t) * DH + d] = kv;
    vOut[((size_t)h * TT + t) * DH + d] = vv;
    size_t ci = ((size_t)h * 4096 + STATE + t) * DH + d;
    uint32_t uk = __float_as_uint(kv);
    kcH[ci] = (unsigned short)(uk >> 16);
    kcL[ci] = __float2bfloat16_rn(kv - __uint_as_float(uk & 0xFFFF0000u));
    uint32_t uv = __float_as_uint(vv);
    vcH[ci] = (unsigned short)(uv >> 16);
    vcL[ci] = __float2bfloat16_rn(vv - __uint_as_float(uv & 0xFFFF0000u));
}

// ================= Flash attention via mma.sync (3-term bf16) ================
// CTA = (head h, q-tile of 32 rows). 256 thr, 8 warps.
// Key tiles of 64; K/V double-buffered cp.async; fp32 online softmax (warp 0).
#define PQB 272u      // Q/K/V smem row pitch bytes (136 bf16)
#define PPB 144u      // P smem row pitch bytes (72 bf16)
#define QH_O  0u
#define QL_O  8704u
#define STG0  17408u
#define STGSZ 69632u  // Kh|Kl|Vh|Vl @ 17408 each
#define SS_O  156672u
#define PH_O  165376u
#define PL_O  169984u
#define SM_O  174592u
#define SL_O  174720u
#define SC_O  174848u
#define ATTN_SMEM 175104
__global__ __launch_bounds__(256) void attn_mma(
    const __nv_bfloat16* __restrict__ qrH, const __nv_bfloat16* __restrict__ qrL,
    const __nv_bfloat16* __restrict__ kcH, const __nv_bfloat16* __restrict__ kcL,
    const __nv_bfloat16* __restrict__ vcH, const __nv_bfloat16* __restrict__ vcL)
{
    extern __shared__ __align__(16) char sm[];
    const uint32_t base = smem_u32(sm);
    const int tid  = threadIdx.x;
    const int lane = tid & 31;
    const int wid  = tid >> 5;
    const int mw   = wid & 1;
    const int wq   = wid >> 1;
    const int h  = blockIdx.x;
    const int qt = blockIdx.y;
    const int g  = h >> 2;
    const int l0 = qt * 32;

    {
        int r = tid >> 3, c = (tid & 7) * 2;
        const uint4* gh = (const uint4*)(qrH + ((size_t)h * LQ + l0 + r) * DH) + c;
        const uint4* gl = (const uint4*)(qrL + ((size_t)h * LQ + l0 + r) * DH) + c;
        uint4* dh = (uint4*)(sm + QH_O + r * PQB) + c;
        uint4* dl = (uint4*)(sm + QL_O + r * PQB) + c;
        dh[0] = gh[0]; dh[1] = gh[1];
        dl[0] = gl[0]; dl[1] = gl[1];
    }
    if (tid < 32) {
        *(float*)(sm + SM_O + tid * 4) = -1e30f;
        *(float*)(sm + SL_O + tid * 4) = 0.0f;
    }

    const int fa = tid >> 6, fr = tid & 63;
    const __nv_bfloat16* farr =
        (fa == 0 ? kcH : fa == 1 ? kcL : fa == 2 ? vcH : vcL) +
        (size_t)(g * 4096 + fr) * DH;
    const uint32_t fdst = base + STG0 + (uint32_t)fa * 17408u + (uint32_t)fr * PQB;

    {
        const __nv_bfloat16* src = farr;
#pragma unroll
        for (int c = 0; c < 16; c++) CPA16(fdst + c * 16, src + c * 8);
        CPA_COMMIT();
    }

    const int ntile = (3968 + l0 + 31) / 64 + 1;

    const uint32_t lmQ = (uint32_t)((16 * mw + (lane & 15)) * PQB + (lane >> 4) * 16);
    const uint32_t lmK = (uint32_t)((16 * wq + (lane & 15)) * PQB + (lane >> 4) * 16);
    const uint32_t lmP = (uint32_t)((16 * mw + (lane & 15)) * PPB + (lane >> 4) * 16);
    const uint32_t lmV = (uint32_t)((lane & 15) * PQB +
                                    (32 * wq + (lane >> 4) * 8) * 2);
    const int r_lo = 16 * mw + (lane >> 2);
    const int r_hi = r_lo + 8;

    float oacc[4][4];
#pragma unroll
    for (int i = 0; i < 4; i++)
#pragma unroll
        for (int e = 0; e < 4; e++) oacc[i][e] = 0.0f;

    for (int t = 0; t < ntile; t++) {
        const int st = t & 1;
        const int s0 = t * 64;
        const uint32_t sg = base + STG0 + (uint32_t)st * STGSZ;

        __syncthreads();
        if (t + 1 < ntile) {
            const __nv_bfloat16* src = farr + (size_t)(t + 1) * 64 * DH;
            const uint32_t d2 = fdst + (uint32_t)(st ^ 1) * STGSZ;
#pragma unroll
            for (int c = 0; c < 16; c++) CPA16(d2 + c * 16, src + c * 8);
        }
        CPA_COMMIT();
        CPA_WAIT1G();
        __syncthreads();

        // ---- scores: S[32,64] = Q * K^T (3-term) ----
        float sacc[2][4];
#pragma unroll
        for (int i = 0; i < 2; i++)
#pragma unroll
            for (int e = 0; e < 4; e++) sacc[i][e] = 0.0f;
#pragma unroll
        for (int kt = 0; kt < 8; kt++) {
            uint32_t qh[4], ql[4], kh[4], kl[4];
            ldm4(qh, base + QH_O + lmQ + kt * 32);
            ldm4(ql, base + QL_O + lmQ + kt * 32);
            ldm4(kh, sg + lmK + kt * 32);
            ldm4(kl, sg + 17408u + lmK + kt * 32);
#pragma unroll
            for (int nt = 0; nt < 2; nt++) {
                mma_bf16(sacc[nt], qh, kh[nt], kh[nt + 2]);
                mma_bf16(sacc[nt], ql, kh[nt], kh[nt + 2]);
                mma_bf16(sacc[nt], qh, kl[nt], kl[nt + 2]);
            }
        }
        {
            int lim_lo = 3968 + l0 + r_lo;
            int lim_hi = lim_lo + 8;
#pragma unroll
            for (int nt = 0; nt < 2; nt++) {
                int c0 = 16 * wq + 8 * nt + (lane & 3) * 2;
                int k0g = s0 + c0;
                float v0 = (k0g     <= lim_lo) ? sacc[nt][0] : -1e30f;
                float v1 = (k0g + 1 <= lim_lo) ? sacc[nt][1] : -1e30f;
                float v2 = (k0g     <= lim_hi) ? sacc[nt][2] : -1e30f;
                float v3 = (k0g + 1 <= lim_hi) ? sacc[nt][3] : -1e30f;
                *(float2*)(sm + SS_O + r_lo * PQB + c0 * 4) = make_float2(v0, v1);
                *(float2*)(sm + SS_O + r_hi * PQB + c0 * 4) = make_float2(v2, v3);
            }
        }
        __syncthreads();

        // ---- online softmax (warp 0), split P into bf16 hi/lo ----
        if (tid < 32) {
            int r = tid;
            float* row = (float*)(sm + SS_O + r * PQB);
            float mOld = *(float*)(sm + SM_O + r * 4);
            float mx = mOld;
            float sv[64];
#pragma unroll
            for (int j = 0; j < 16; j++) {
                float4 q4 = ((float4*)row)[j];
                sv[4*j] = q4.x; sv[4*j+1] = q4.y; sv[4*j+2] = q4.z; sv[4*j+3] = q4.w;
                mx = fmaxf(mx, fmaxf(fmaxf(q4.x, q4.y), fmaxf(q4.z, q4.w)));
            }
            float c = __expf(mOld - mx);
            float sum = 0.0f;
            uint32_t* ph = (uint32_t*)(sm + PH_O + r * PPB);
            uint32_t* pl = (uint32_t*)(sm + PL_O + r * PPB);
#pragma unroll
            for (int j = 0; j < 32; j++) {
                float e0 = __expf(sv[2*j]   - mx);
                float e1 = __expf(sv[2*j+1] - mx);
                sum += e0 + e1;
                uint32_t u0 = __float_as_uint(e0), u1 = __float_as_uint(e1);
                ph[j] = __byte_perm(u0, u1, 0x7632);
                float f0 = e0 - __uint_as_float(u0 & 0xFFFF0000u);
                float f1 = e1 - __uint_as_float(u1 & 0xFFFF0000u);
                __nv_bfloat162 p = __float22bfloat162_rn(make_float2(f0, f1));
                pl[j] = *(uint32_t*)&p;
            }
            *(float*)(sm + SM_O + r * 4) = mx;
            *(float*)(sm + SL_O + r * 4) =
                *(float*)(sm + SL_O + r * 4) * c + sum;
            *(float*)(sm + SC_O + r * 4) = c;
        }
        __syncthreads();

        // ---- PV: O[32,128] += P[32,64] * V[64,128] (3-term) ----
        {
            float c_lo = *(float*)(sm + SC_O + r_lo * 4);
            float c_hi = *(float*)(sm + SC_O + r_hi * 4);
#pragma unroll
            for (int nt = 0; nt < 4; nt++) {
                oacc[nt][0] *= c_lo; oacc[nt][1] *= c_lo;
                oacc[nt][2] *= c_hi; oacc[nt][3] *= c_hi;
            }
        }
        const uint32_t vgh = sg + 34816u;
        const uint32_t vgl = sg + 52224u;
#pragma unroll
        for (int kt = 0; kt < 4; kt++) {
            uint32_t ph4[4], pl4[4];
            ldm4(ph4, base + PH_O + lmP + kt * 32);
            ldm4(pl4, base + PL_O + lmP + kt * 32);
            uint32_t vrow = (uint32_t)(16 * kt) * PQB + lmV;
            uint32_t vh[4], vl[4];
            ldm4t(vh, vgh + vrow);
            ldm4t(vl, vgl + vrow);
            mma_bf16(oacc[0], ph4, vh[0], vh[1]);
            mma_bf16(oacc[0], pl4, vh[0], vh[1]);
            mma_bf16(oacc[0], ph4, vl[0], vl[1]);
            mma_bf16(oacc[1], ph4, vh[2], vh[3]);
            mma_bf16(oacc[1], pl4, vh[2], vh[3]);
            mma_bf16(oacc[1], ph4, vl[2], vl[3]);
            uint32_t vrow2 = vrow + 32;
            ldm4t(vh, vgh + vrow2);
            ldm4t(vl, vgl + vrow2);
            mma_bf16(oacc[2], ph4, vh[0], vh[1]);
            mma_bf16(oacc[2], pl4, vh[0], vh[1]);
            mma_bf16(oacc[2], ph4, vl[0], vl[1]);
            mma_bf16(oacc[3], ph4, vh[2], vh[3]);
            mma_bf16(oacc[3], pl4, vh[2], vh[3]);
            mma_bf16(oacc[3], ph4, vl[2], vl[3]);
        }
    }

    float inv_lo = 1.0f / *(float*)(sm + SL_O + r_lo * 4);
    float inv_hi = 1.0f / *(float*)(sm + SL_O + r_hi * 4);
#pragma unroll
    for (int nt = 0; nt < 4; nt++) {
        int d = 32 * wq + 8 * nt + (lane & 3) * 2;
        float* p0 = g_o + (size_t)(l0 + r_lo) * HID + h * DH + d;
        float* p1 = g_o + (size_t)(l0 + r_hi) * HID + h * DH + d;
        *(float2*)p0 = make_float2(oacc[nt][0] * inv_lo, oacc[nt][1] * inv_lo);
        *(float2*)p1 = make_float2(oacc[nt][2] * inv_hi, oacc[nt][3] * inv_hi);
    }
}

// ---------------- launch ----------------
extern "C" void kernel_launch(void* const* d_in, const int* in_sizes, int n_in,
                              void* d_out, int out_size) {
    const float* x     = (const float*)d_in[0];
    const float* xctx  = (const float*)d_in[1];
    const float* cosq  = (const float*)d_in[2];
    const float* sinq  = (const float*)d_in[3];
    const float* cosk  = (const float*)d_in[4];
    const float* sink  = (const float*)d_in[5];
    const float* cK    = (const float*)d_in[6];
    const float* cV    = (const float*)d_in[7];
    const float* Wq    = (const float*)d_in[9];
    const float* Wk    = (const float*)d_in[10];
    const float* Wv    = (const float*)d_in[11];
    const float* Wo    = (const float*)d_in[12];
    const float* qw    = (const float*)d_in[13];
    const float* kw    = (const float*)d_in[14];

    float* out  = (float*)d_out;
    float* kOut = out + (size_t)LQ * HID;
    float* vOut = kOut + (size_t)HKV * TT * DH;

    cudaFuncSetAttribute(gemm_bf3, cudaFuncAttributeMaxDynamicSharedMemorySize,
                         81920);
    cudaFuncSetAttribute(attn_mma, cudaFuncAttributeMaxDynamicSharedMemorySize,
                         ATTN_SMEM);

    __nv_bfloat16 *actH, *actL, *wqH, *wqL, *wkH, *wkL, *wvH, *wvL,
                  *woH, *woL, *goH, *goL, *qrH, *qrL, *kcH, *kcL, *vcH, *vcL;
    cudaGetSymbolAddress((void**)&actH, c_actH);
    cudaGetSymbolAddress((void**)&actL, c_actL);
    cudaGetSymbolAddress((void**)&wqH,  c_wqH);
    cudaGetSymbolAddress((void**)&wqL,  c_wqL);
    cudaGetSymbolAddress((void**)&wkH,  c_wkH);
    cudaGetSymbolAddress((void**)&wkL,  c_wkL);
    cudaGetSymbolAddress((void**)&wvH,  c_wvH);
    cudaGetSymbolAddress((void**)&wvL,  c_wvL);
    cudaGetSymbolAddress((void**)&woH,  c_woH);
    cudaGetSymbolAddress((void**)&woL,  c_woL);
    cudaGetSymbolAddress((void**)&goH,  c_goH);
    cudaGetSymbolAddress((void**)&goL,  c_goL);
    cudaGetSymbolAddress((void**)&qrH,  c_qrH);
    cudaGetSymbolAddress((void**)&qrL,  c_qrL);
    cudaGetSymbolAddress((void**)&kcH,  c_kcH);
    cudaGetSymbolAddress((void**)&kcL,  c_kcL);
    cudaGetSymbolAddress((void**)&vcH,  c_vcH);
    cudaGetSymbolAddress((void**)&vcL,  c_vcL);
    float *gq, *go;
    cudaGetSymbolAddress((void**)&gq, g_q);
    cudaGetSymbolAddress((void**)&go, g_o);
    float *gk, *gv;
    cudaGetSymbolAddress((void**)&gk, g_k);
    cudaGetSymbolAddress((void**)&gv, g_v);

    cache_split<<<(2 * CCH4 + 255) / 256, 256>>>(
        (const float4*)cK, (const float4*)cV,
        (uint2*)kcH, (uint2*)kcL, (uint2*)vcH, (uint2*)vcL);
    cvt_a<<<(ACT4 + 255) / 256, 256>>>((const float4*)xctx, (const float4*)x,
                                       (uint2*)actH, (uint2*)actL);
    {
        long long tot = 2LL * WQ4 + 2LL * WK4;
        cvt_w<<<(unsigned)((tot + 255) / 256), 256>>>(
            (const float4*)Wq, (const float4*)Wk, (const float4*)Wv,
            (const float4*)Wo,
            (uint2*)wqH, (uint2*)wqL, (uint2*)wkH, (uint2*)wkL,
            (uint2*)wvH, (uint2*)wvL, (uint2*)woH, (uint2*)woL);
    }
    gemm_bf3<<<dim3(64, 2, 1), 256, 81920>>>(
        actH + (size_t)CTXN * HID, actL + (size_t)CTXN * HID,
        wqH, wqL, wqH, wqL, gq, gq, HID);
    gemm_bf3<<<dim3(16, 16, 2), 256, 81920>>>(
        actH, actL, wkH, wkL, wvH, wvL, gk, gv, HKV * DH);
    qnorm_k<<<dim3(HQ, LQ), 128>>>(cosq, sinq, qw,
                                   (unsigned short*)qrH, qrL);
    kvnorm_k<<<dim3(HKV, TT), 128>>>(cosk, sink, kw, kOut, vOut,
                                     (unsigned short*)kcH, kcL,
                                     (unsigned short*)vcH, vcL);
    attn_mma<<<dim3(HQ, 4), 256, ATTN_SMEM>>>(qrH, qrL, kcH, kcL, vcH, vcL);
    cvt_go<<<(LQ * HID / 4 + 255) / 256, 256>>>((const float4*)go,
                                                (uint2*)goH, (uint2*)goL,
                                                LQ * HID / 4);
    gemm_bf3<<<dim3(64, 2, 1), 256, 81920>>>(
        goH, goL, woH, woL, woH, woL, out, out, HID);
}

// round 14
// speedup vs baseline: 1.8254x; 1.0120x over previous
#include <cuda_runtime.h>
#include <cuda_bf16.h>
#include <cstdint>
#include <cstddef>

#define HID   4096
#define LQ    128
#define CTXN  896
#define TT    1024
#define STATE 3072
#define HQ    32
#define HKV   8
#define DH    128
#define SCALE 0.08838834764831845f
#define NEPS  1e-6f

// ---------------- scratch (device globals; no allocation APIs) ----------------
__device__ __align__(16) float g_q [LQ * HID];
__device__ __align__(16) float g_k [TT * HKV * DH];
__device__ __align__(16) float g_v [TT * HKV * DH];
__device__ __align__(16) float g_o [LQ * HID];

__device__ __align__(16) __nv_bfloat16 c_actH[TT * HID];
__device__ __align__(16) __nv_bfloat16 c_actL[TT * HID];
__device__ __align__(16) __nv_bfloat16 c_wqH [HID * HID];
__device__ __align__(16) __nv_bfloat16 c_wqL [HID * HID];
__device__ __align__(16) __nv_bfloat16 c_wkH [HKV * DH * HID];
__device__ __align__(16) __nv_bfloat16 c_wkL [HKV * DH * HID];
__device__ __align__(16) __nv_bfloat16 c_wvH [HKV * DH * HID];
__device__ __align__(16) __nv_bfloat16 c_wvL [HKV * DH * HID];
__device__ __align__(16) __nv_bfloat16 c_woH [HID * HID];
__device__ __align__(16) __nv_bfloat16 c_woL [HID * HID];
__device__ __align__(16) __nv_bfloat16 c_goH [LQ * HID];
__device__ __align__(16) __nv_bfloat16 c_goL [LQ * HID];

// attention operands, pre-split
__device__ __align__(16) __nv_bfloat16 c_qrH[HQ * LQ * DH];
__device__ __align__(16) __nv_bfloat16 c_qrL[HQ * LQ * DH];
__device__ __align__(16) __nv_bfloat16 c_kcH[HKV * 4096 * DH];
__device__ __align__(16) __nv_bfloat16 c_kcL[HKV * 4096 * DH];
__device__ __align__(16) __nv_bfloat16 c_vcH[HKV * 4096 * DH];
__device__ __align__(16) __nv_bfloat16 c_vcL[HKV * 4096 * DH];

// ---------------- mma helpers ----------------
static __device__ __forceinline__ uint32_t smem_u32(const void* p) {
    uint32_t a;
    asm("{ .reg .u64 t; cvta.to.shared.u64 t, %1; cvt.u32.u64 %0, t; }"
        : "=r"(a) : "l"(p));
    return a;
}
static __device__ __forceinline__ void ldm4(uint32_t* r, uint32_t addr) {
    asm volatile("ldmatrix.sync.aligned.m8n8.x4.shared.b16 {%0,%1,%2,%3}, [%4];"
                 : "=r"(r[0]), "=r"(r[1]), "=r"(r[2]), "=r"(r[3]) : "r"(addr));
}
static __device__ __forceinline__ void ldm4t(uint32_t* r, uint32_t addr) {
    asm volatile("ldmatrix.sync.aligned.m8n8.x4.trans.shared.b16 {%0,%1,%2,%3}, [%4];"
                 : "=r"(r[0]), "=r"(r[1]), "=r"(r[2]), "=r"(r[3]) : "r"(addr));
}
static __device__ __forceinline__ void mma_bf16(float* c, const uint32_t* a,
                                                uint32_t b0, uint32_t b1) {
    asm volatile(
        "mma.sync.aligned.m16n8k16.row.col.f32.bf16.bf16.f32 "
        "{%0,%1,%2,%3}, {%4,%5,%6,%7}, {%8,%9}, {%0,%1,%2,%3};"
        : "+f"(c[0]), "+f"(c[1]), "+f"(c[2]), "+f"(c[3])
        : "r"(a[0]), "r"(a[1]), "r"(a[2]), "r"(a[3]), "r"(b0), "r"(b1));
}
#define CPA16(dst, src) \
    asm volatile("cp.async.cg.shared.global [%0], [%1], 16;" \
                 :: "r"(dst), "l"(src) : "memory")
#define CPA_COMMIT() asm volatile("cp.async.commit_group;" ::: "memory")
#define CPA_WAIT2()  asm volatile("cp.async.wait_group 2;" ::: "memory")
#define CPA_WAIT1G() asm volatile("cp.async.wait_group 1;" ::: "memory")

// ---------------- fp32 -> (hi, lo) split core ----------------
static __device__ __forceinline__ void split4(float4 f, uint2& h, uint2& l) {
    uint32_t u0 = __float_as_uint(f.x), u1 = __float_as_uint(f.y);
    uint32_t u2 = __float_as_uint(f.z), u3 = __float_as_uint(f.w);
    h.x = __byte_perm(u0, u1, 0x7632);
    h.y = __byte_perm(u2, u3, 0x7632);
    float l0 = f.x - __uint_as_float(u0 & 0xFFFF0000u);
    float l1 = f.y - __uint_as_float(u1 & 0xFFFF0000u);
    float l2 = f.z - __uint_as_float(u2 & 0xFFFF0000u);
    float l3 = f.w - __uint_as_float(u3 & 0xFFFF0000u);
    __nv_bfloat162 p0 = __float22bfloat162_rn(make_float2(l0, l1));
    __nv_bfloat162 p1 = __float22bfloat162_rn(make_float2(l2, l3));
    l.x = *(uint32_t*)&p0;
    l.y = *(uint32_t*)&p1;
}

// acts: concat(xctx, x) -> c_act{H,L}
#define ACT4   (TT * HID / 4)
#define CTX4   (CTXN * HID / 4)
__global__ __launch_bounds__(256) void cvt_a(
    const float4* __restrict__ xctx, const float4* __restrict__ x,
    uint2* __restrict__ hi, uint2* __restrict__ lo)
{
    int i = blockIdx.x * 256 + threadIdx.x;
    if (i >= ACT4) return;
    float4 f = (i < CTX4) ? xctx[i] : x[i - CTX4];
    uint2 h, l; split4(f, h, l);
    hi[i] = h; lo[i] = l;
}

// weights: Wq | Wk | Wv | Wo
#define WQ4 (HID * HID / 4)
#define WK4 (HKV * DH * HID / 4)
__global__ __launch_bounds__(256) void cvt_w(
    const float4* __restrict__ wq, const float4* __restrict__ wk,
    const float4* __restrict__ wv, const float4* __restrict__ wo,
    uint2* __restrict__ qH, uint2* __restrict__ qL,
    uint2* __restrict__ kH, uint2* __restrict__ kL,
    uint2* __restrict__ vH, uint2* __restrict__ vL,
    uint2* __restrict__ oH, uint2* __restrict__ oL)
{
    long long i = (long long)blockIdx.x * 256 + threadIdx.x;
    const long long s0 = WQ4, s1 = s0 + WK4, s2 = s1 + WK4, s3 = s2 + WQ4;
    if (i >= s3) return;
    const float4* src; uint2 *dh, *dl; long long j;
    if      (i < s0) { src = wq; dh = qH; dl = qL; j = i; }
    else if (i < s1) { src = wk; dh = kH; dl = kL; j = i - s0; }
    else if (i < s2) { src = wv; dh = vH; dl = vL; j = i - s1; }
    else             { src = wo; dh = oH; dl = oL; j = i - s2; }
    uint2 h, l; split4(src[j], h, l);
    dh[j] = h; dl[j] = l;
}

__global__ __launch_bounds__(256) void cvt_go(
    const float4* __restrict__ src, uint2* __restrict__ hi,
    uint2* __restrict__ lo, int n4)
{
    int i = blockIdx.x * 256 + threadIdx.x;
    if (i >= n4) return;
    uint2 h, l; split4(src[i], h, l);
    hi[i] = h; lo[i] = l;
}

// cache region of kcat/vcat: split cK/cV (s < 3072) into bf16 hi/lo
#define CCH4 (HKV * STATE * DH / 4)
__global__ __launch_bounds__(256) void cache_split(
    const float4* __restrict__ cK, const float4* __restrict__ cV,
    uint2* __restrict__ kH, uint2* __restrict__ kL,
    uint2* __restrict__ vH, uint2* __restrict__ vL)
{
    int i = blockIdx.x * 256 + threadIdx.x;
    if (i >= 2 * CCH4) return;
    const float4* src = (i < CCH4) ? cK : cV;
    uint2 *dh = (i < CCH4) ? kH : vH;
    uint2 *dl = (i < CCH4) ? kL : vL;
    int j = (i < CCH4) ? i : i - CCH4;
    int e = j * 4;
    int g = e / (STATE * DH);
    int rem = e - g * (STATE * DH);
    int s = rem / DH;
    int d = rem - s * DH;
    uint2 h, l; split4(src[j], h, l);
    size_t dst = ((size_t)(g * 4096 + s) * DH + d) / 4;
    dh[dst] = h; dl[dst] = l;
}

// ============ GEMM (R5 config): C[M,N] = A[M,4096] * B[N,4096]^T ============
#define GP       40
#define ARR_B    5120u
#define STG_B    20480u
__global__ __launch_bounds__(256) void gemm_bf3(
    const __nv_bfloat16* __restrict__ aH, const __nv_bfloat16* __restrict__ aL,
    const __nv_bfloat16* __restrict__ bH0, const __nv_bfloat16* __restrict__ bL0,
    const __nv_bfloat16* __restrict__ bH1, const __nv_bfloat16* __restrict__ bL1,
    float* __restrict__ C0, float* __restrict__ C1, int ldc)
{
    extern __shared__ __align__(16) char sm[];
    const int tid  = threadIdx.x;
    const int lane = tid & 31;
    const int wid  = tid >> 5;
    const int wm   = wid >> 2;
    const int wn   = wid & 3;
    const int m0   = blockIdx.y * 64;
    const int n0   = blockIdx.x * 64;
    const int z    = blockIdx.z;

    const __nv_bfloat16* bH = z ? bH1 : bH0;
    const __nv_bfloat16* bL = z ? bL1 : bL0;
    float* C = z ? C1 : C0;

    const int row = tid >> 2, c4 = tid & 3;
    const __nv_bfloat16* gaH = aH + (size_t)(m0 + row) * 4096 + c4 * 8;
    const __nv_bfloat16* gaL = aL + (size_t)(m0 + row) * 4096 + c4 * 8;
    const __nv_bfloat16* gbH = bH + (size_t)(n0 + row) * 4096 + c4 * 8;
    const __nv_bfloat16* gbL = bL + (size_t)(n0 + row) * 4096 + c4 * 8;

    const uint32_t smBase = smem_u32(sm);
    const uint32_t sOff   = (uint32_t)(row * 80 + c4 * 16);

    const int mrl = (lane & 7) + ((lane >> 3) & 1) * 8;
    const int kof = ((lane >> 4) & 1) * 8;
    const uint32_t aoff = (uint32_t)(((32 * wm + mrl) * GP + kof) * 2);
    const uint32_t boff = (uint32_t)(((16 * wn + mrl) * GP + kof) * 2);

    float acc[2][2][4];
#pragma unroll
    for (int i = 0; i < 2; i++)
#pragma unroll
        for (int j = 0; j < 2; j++)
#pragma unroll
            for (int e = 0; e < 4; e++) acc[i][j][e] = 0.0f;

#pragma unroll
    for (int p = 0; p < 3; p++) {
        uint32_t d = smBase + (uint32_t)p * STG_B + sOff;
        int k0 = p * 32;
        CPA16(d,             gaH + k0);
        CPA16(d + ARR_B,     gaL + k0);
        CPA16(d + 2 * ARR_B, gbH + k0);
        CPA16(d + 3 * ARR_B, gbL + k0);
        CPA_COMMIT();
    }

    const int NK = 128;
    for (int ic = 0; ic < NK; ic++) {
        CPA_WAIT2();
        __syncthreads();

        const uint32_t sb = smBase + (uint32_t)(ic & 3) * STG_B;
#pragma unroll
        for (int ks = 0; ks < 2; ks++) {
            const uint32_t kb = (uint32_t)ks * 32;
            uint32_t Ah[2][4], Al[2][4], Bh[4], Bl[4];
            ldm4(Ah[0], sb + aoff + kb);
            ldm4(Ah[1], sb + aoff + 16 * GP * 2 + kb);
            ldm4(Al[0], sb + ARR_B + aoff + kb);
            ldm4(Al[1], sb + ARR_B + aoff + 16 * GP * 2 + kb);
            ldm4(Bh,    sb + 2 * ARR_B + boff + kb);
            ldm4(Bl,    sb + 3 * ARR_B + boff + kb);
#pragma unroll
            for (int tm = 0; tm < 2; tm++)
#pragma unroll
                for (int tn = 0; tn < 2; tn++) {
                    mma_bf16(acc[tm][tn], Ah[tm], Bh[tn], Bh[tn + 2]);
                    mma_bf16(acc[tm][tn], Al[tm], Bh[tn], Bh[tn + 2]);
                    mma_bf16(acc[tm][tn], Ah[tm], Bl[tn], Bl[tn + 2]);
                }
        }

        if (ic + 3 < NK) {
            int k0 = (ic + 3) * 32;
            uint32_t d = smBase + (uint32_t)((ic + 3) & 3) * STG_B + sOff;
            CPA16(d,             gaH + k0);
            CPA16(d + ARR_B,     gaL + k0);
            CPA16(d + 2 * ARR_B, gbH + k0);
            CPA16(d + 3 * ARR_B, gbL + k0);
        }
        CPA_COMMIT();
    }

    const int r0 = m0 + 32 * wm + (lane >> 2);
    const int c0 = n0 + 16 * wn + (lane & 3) * 2;
#pragma unroll
    for (int tm = 0; tm < 2; tm++)
#pragma unroll
        for (int tn = 0; tn < 2; tn++) {
            float* p = C + (size_t)(r0 + 16 * tm) * ldc + c0 + 8 * tn;
            *(float2*)p = make_float2(acc[tm][tn][0], acc[tm][tn][1]);
            float* p2 = p + (size_t)8 * ldc;
            *(float2*)p2 = make_float2(acc[tm][tn][2], acc[tm][tn][3]);
        }
}

// ---------------- ane-norm + RoPE + scale for Q -> split bf16 ----------------
__global__ __launch_bounds__(128) void qnorm_k(
    const float* __restrict__ cq, const float* __restrict__ sq,
    const float* __restrict__ w,
    unsigned short* __restrict__ qrH, __nv_bfloat16* __restrict__ qrL)
{
    int h = blockIdx.x, l = blockIdx.y, d = threadIdx.x;
    __shared__ float red[8];
    __shared__ float xs[128];
    float v = g_q[l * HID + h * DH + d];
    float s1 = v, s2 = v * v;
#pragma unroll
    for (int off = 16; off; off >>= 1) {
        s1 += __shfl_down_sync(0xffffffffu, s1, off);
        s2 += __shfl_down_sync(0xffffffffu, s2, off);
    }
    if ((d & 31) == 0) { red[d >> 5] = s1; red[4 + (d >> 5)] = s2; }
    __syncthreads();
    float sum = red[0] + red[1] + red[2] + red[3];
    float sqs = red[4] + red[5] + red[6] + red[7];
    float mean = sum * (1.0f / 128.0f);
    float var  = sqs * (1.0f / 128.0f) - mean * mean;
    float xn = (v - mean) * rsqrtf(var + NEPS) * w[d];
    xs[d] = xn;
    __syncthreads();
    float rot = (d < 64) ? -xs[d + 64] : xs[d - 64];
    float o = (xn * cq[l * DH + d] + rot * sq[l * DH + d]) * SCALE;
    size_t idx = ((size_t)h * LQ + l) * DH + d;
    uint32_t u = __float_as_uint(o);
    qrH[idx] = (unsigned short)(u >> 16);
    qrL[idx] = __float2bfloat16_rn(o - __uint_as_float(u & 0xFFFF0000u));
}

// ---------- ane-norm + RoPE for K; outputs fp32 k/v + split kcat/vcat --------
__global__ __launch_bounds__(128) void kvnorm_k(
    const float* __restrict__ ck, const float* __restrict__ sk,
    const float* __restrict__ w,
    float* __restrict__ kOut, float* __restrict__ vOut,
    unsigned short* __restrict__ kcH, __nv_bfloat16* __restrict__ kcL,
    unsigned short* __restrict__ vcH, __nv_bfloat16* __restrict__ vcL)
{
    int h = blockIdx.x, t = blockIdx.y, d = threadIdx.x;
    __shared__ float red[8];
    __shared__ float xs[128];
    float v = g_k[t * (HKV * DH) + h * DH + d];
    float s1 = v, s2 = v * v;
#pragma unroll
    for (int off = 16; off; off >>= 1) {
        s1 += __shfl_down_sync(0xffffffffu, s1, off);
        s2 += __shfl_down_sync(0xffffffffu, s2, off);
    }
    if ((d & 31) == 0) { red[d >> 5] = s1; red[4 + (d >> 5)] = s2; }
    __syncthreads();
    float sum = red[0] + red[1] + red[2] + red[3];
    float sqs = red[4] + red[5] + red[6] + red[7];
    float mean = sum * (1.0f / 128.0f);
    float var  = sqs * (1.0f / 128.0f) - mean * mean;
    float xn = (v - mean) * rsqrtf(var + NEPS) * w[d];
    xs[d] = xn;
    __syncthreads();
    float rot = (d < 64) ? -xs[d + 64] : xs[d - 64];
    float kv = xn * ck[t * DH + d] + rot * sk[t * DH + d];
    float vv = g_v[t * (HKV * DH) + h * DH + d];
    kOut[((size_t)h * TT + t) * DH + d] = kv;
    vOut[((size_t)h * TT + t) * DH + d] = vv;
    size_t ci = ((size_t)h * 4096 + STATE + t) * DH + d;
    uint32_t uk = __float_as_uint(kv);
    kcH[ci] = (unsigned short)(uk >> 16);
    kcL[ci] = __float2bfloat16_rn(kv - __uint_as_float(uk & 0xFFFF0000u));
    uint32_t uv = __float_as_uint(vv);
    vcH[ci] = (unsigned short)(uv >> 16);
    vcL[ci] = __float2bfloat16_rn(vv - __uint_as_float(uv & 0xFFFF0000u));
}

// ================= Flash attention via mma.sync (3-term bf16) ================
// CTA = (head h, q-tile of 32 rows). 256 thr, 8 warps.
// Key tiles of 64; K/V double-buffered cp.async; parallel online softmax.
#define PQB 272u      // Q/K/V smem row pitch bytes (136 bf16)
#define PPB 144u      // P smem row pitch bytes (72 bf16)
#define QH_O  0u
#define QL_O  8704u
#define STG0  17408u
#define STGSZ 69632u  // Kh|Kl|Vh|Vl @ 17408 each
#define SS_O  156672u
#define PH_O  165376u
#define PL_O  169984u
#define SM_O  174592u
#define SL_O  174720u
#define SC_O  174848u
#define ATTN_SMEM 175104
__global__ __launch_bounds__(256) void attn_mma(
    const __nv_bfloat16* __restrict__ qrH, const __nv_bfloat16* __restrict__ qrL,
    const __nv_bfloat16* __restrict__ kcH, const __nv_bfloat16* __restrict__ kcL,
    const __nv_bfloat16* __restrict__ vcH, const __nv_bfloat16* __restrict__ vcL)
{
    extern __shared__ __align__(16) char sm[];
    const uint32_t base = smem_u32(sm);
    const int tid  = threadIdx.x;
    const int lane = tid & 31;
    const int wid  = tid >> 5;
    const int mw   = wid & 1;
    const int wq   = wid >> 1;
    const int h  = blockIdx.x;
    const int qt = blockIdx.y;
    const int g  = h >> 2;
    const int l0 = qt * 32;

    {
        int r = tid >> 3, c = (tid & 7) * 2;
        const uint4* gh = (const uint4*)(qrH + ((size_t)h * LQ + l0 + r) * DH) + c;
        const uint4* gl = (const uint4*)(qrL + ((size_t)h * LQ + l0 + r) * DH) + c;
        uint4* dh = (uint4*)(sm + QH_O + r * PQB) + c;
        uint4* dl = (uint4*)(sm + QL_O + r * PQB) + c;
        dh[0] = gh[0]; dh[1] = gh[1];
        dl[0] = gl[0]; dl[1] = gl[1];
    }
    if (tid < 32) {
        *(float*)(sm + SM_O + tid * 4) = -1e30f;
        *(float*)(sm + SL_O + tid * 4) = 0.0f;
    }

    const int fa = tid >> 6, fr = tid & 63;
    const __nv_bfloat16* farr =
        (fa == 0 ? kcH : fa == 1 ? kcL : fa == 2 ? vcH : vcL) +
        (size_t)(g * 4096 + fr) * DH;
    const uint32_t fdst = base + STG0 + (uint32_t)fa * 17408u + (uint32_t)fr * PQB;

    {
        const __nv_bfloat16* src = farr;
#pragma unroll
        for (int c = 0; c < 16; c++) CPA16(fdst + c * 16, src + c * 8);
        CPA_COMMIT();
    }

    const int ntile = (3968 + l0 + 31) / 64 + 1;

    const uint32_t lmQ = (uint32_t)((16 * mw + (lane & 15)) * PQB + (lane >> 4) * 16);
    const uint32_t lmK = (uint32_t)((16 * wq + (lane & 15)) * PQB + (lane >> 4) * 16);
    const uint32_t lmP = (uint32_t)((16 * mw + (lane & 15)) * PPB + (lane >> 4) * 16);
    const uint32_t lmV = (uint32_t)((lane & 15) * PQB +
                                    (32 * wq + (lane >> 4) * 8) * 2);
    const int r_lo = 16 * mw + (lane >> 2);
    const int r_hi = r_lo + 8;

    float oacc[4][4];
#pragma unroll
    for (int i = 0; i < 4; i++)
#pragma unroll
        for (int e = 0; e < 4; e++) oacc[i][e] = 0.0f;

    for (int t = 0; t < ntile; t++) {
        const int st = t & 1;
        const int s0 = t * 64;
        const uint32_t sg = base + STG0 + (uint32_t)st * STGSZ;

        __syncthreads();
        if (t + 1 < ntile) {
            const __nv_bfloat16* src = farr + (size_t)(t + 1) * 64 * DH;
            const uint32_t d2 = fdst + (uint32_t)(st ^ 1) * STGSZ;
#pragma unroll
            for (int c = 0; c < 16; c++) CPA16(d2 + c * 16, src + c * 8);
        }
        CPA_COMMIT();
        CPA_WAIT1G();
        __syncthreads();

        // ---- scores: S[32,64] = Q * K^T (3-term) ----
        float sacc[2][4];
#pragma unroll
        for (int i = 0; i < 2; i++)
#pragma unroll
            for (int e = 0; e < 4; e++) sacc[i][e] = 0.0f;
#pragma unroll
        for (int kt = 0; kt < 8; kt++) {
            uint32_t qh[4], ql[4], kh[4], kl[4];
            ldm4(qh, base + QH_O + lmQ + kt * 32);
            ldm4(ql, base + QL_O + lmQ + kt * 32);
            ldm4(kh, sg + lmK + kt * 32);
            ldm4(kl, sg + 17408u + lmK + kt * 32);
#pragma unroll
            for (int nt = 0; nt < 2; nt++) {
                mma_bf16(sacc[nt], qh, kh[nt], kh[nt + 2]);
                mma_bf16(sacc[nt], ql, kh[nt], kh[nt + 2]);
                mma_bf16(sacc[nt], qh, kl[nt], kl[nt + 2]);
            }
        }
        {
            int lim_lo = 3968 + l0 + r_lo;
            int lim_hi = lim_lo + 8;
#pragma unroll
            for (int nt = 0; nt < 2; nt++) {
                int c0 = 16 * wq + 8 * nt + (lane & 3) * 2;
                int k0g = s0 + c0;
                float v0 = (k0g     <= lim_lo) ? sacc[nt][0] : -1e30f;
                float v1 = (k0g + 1 <= lim_lo) ? sacc[nt][1] : -1e30f;
                float v2 = (k0g     <= lim_hi) ? sacc[nt][2] : -1e30f;
                float v3 = (k0g + 1 <= lim_hi) ? sacc[nt][3] : -1e30f;
                *(float2*)(sm + SS_O + r_lo * PQB + c0 * 4) = make_float2(v0, v1);
                *(float2*)(sm + SS_O + r_hi * PQB + c0 * 4) = make_float2(v2, v3);
            }
        }
        __syncthreads();

        // ---- parallel online softmax: 8 threads per row (all 256 threads) ----
        {
            int r = tid >> 3, cg = tid & 7;
            float* row = (float*)(sm + SS_O + r * PQB);
            float4 a = ((float4*)row)[cg * 2];
            float4 b = ((float4*)row)[cg * 2 + 1];
            float mx = fmaxf(fmaxf(fmaxf(a.x, a.y), fmaxf(a.z, a.w)),
                             fmaxf(fmaxf(b.x, b.y), fmaxf(b.z, b.w)));
#pragma unroll
            for (int o = 1; o < 8; o <<= 1)
                mx = fmaxf(mx, __shfl_xor_sync(0xffffffffu, mx, o));
            float mOld = *(float*)(sm + SM_O + r * 4);
            mx = fmaxf(mx, mOld);
            float e[8];
            e[0] = __expf(a.x - mx); e[1] = __expf(a.y - mx);
            e[2] = __expf(a.z - mx); e[3] = __expf(a.w - mx);
            e[4] = __expf(b.x - mx); e[5] = __expf(b.y - mx);
            e[6] = __expf(b.z - mx); e[7] = __expf(b.w - mx);
            float s = ((e[0] + e[1]) + (e[2] + e[3])) +
                      ((e[4] + e[5]) + (e[6] + e[7]));
#pragma unroll
            for (int o = 1; o < 8; o <<= 1)
                s += __shfl_xor_sync(0xffffffffu, s, o);
            uint32_t* ph = (uint32_t*)(sm + PH_O + r * PPB) + cg * 4;
            uint32_t* pl = (uint32_t*)(sm + PL_O + r * PPB) + cg * 4;
#pragma unroll
            for (int j = 0; j < 4; j++) {
                uint32_t u0 = __float_as_uint(e[2 * j]);
                uint32_t u1 = __float_as_uint(e[2 * j + 1]);
                ph[j] = __byte_perm(u0, u1, 0x7632);
                float f0 = e[2 * j]     - __uint_as_float(u0 & 0xFFFF0000u);
                float f1 = e[2 * j + 1] - __uint_as_float(u1 & 0xFFFF0000u);
                __nv_bfloat162 p = __float22bfloat162_rn(make_float2(f0, f1));
                pl[j] = *(uint32_t*)&p;
            }
            if (cg == 0) {
                float c = __expf(mOld - mx);
                *(float*)(sm + SM_O + r * 4) = mx;
                *(float*)(sm + SL_O + r * 4) =
                    *(float*)(sm + SL_O + r * 4) * c + s;
                *(float*)(sm + SC_O + r * 4) = c;
            }
        }
        __syncthreads();

        // ---- PV: O[32,128] += P[32,64] * V[64,128] (3-term) ----
        {
            float c_lo = *(float*)(sm + SC_O + r_lo * 4);
            float c_hi = *(float*)(sm + SC_O + r_hi * 4);
#pragma unroll
            for (int nt = 0; nt < 4; nt++) {
                oacc[nt][0] *= c_lo; oacc[nt][1] *= c_lo;
                oacc[nt][2] *= c_hi; oacc[nt][3] *= c_hi;
            }
        }
        const uint32_t vgh = sg + 34816u;
        const uint32_t vgl = sg + 52224u;
#pragma unroll
        for (int kt = 0; kt < 4; kt++) {
            uint32_t ph4[4], pl4[4];
            ldm4(ph4, base + PH_O + lmP + kt * 32);
            ldm4(pl4, base + PL_O + lmP + kt * 32);
            uint32_t vrow = (uint32_t)(16 * kt) * PQB + lmV;
            uint32_t vh[4], vl[4];
            ldm4t(vh, vgh + vrow);
            ldm4t(vl, vgl + vrow);
            mma_bf16(oacc[0], ph4, vh[0], vh[1]);
            mma_bf16(oacc[0], pl4, vh[0], vh[1]);
            mma_bf16(oacc[0], ph4, vl[0], vl[1]);
            mma_bf16(oacc[1], ph4, vh[2], vh[3]);
            mma_bf16(oacc[1], pl4, vh[2], vh[3]);
            mma_bf16(oacc[1], ph4, vl[2], vl[3]);
            uint32_t vrow2 = vrow + 32;
            ldm4t(vh, vgh + vrow2);
            ldm4t(vl, vgl + vrow2);
            mma_bf16(oacc[2], ph4, vh[0], vh[1]);
            mma_bf16(oacc[2], pl4, vh[0], vh[1]);
            mma_bf16(oacc[2], ph4, vl[0], vl[1]);
            mma_bf16(oacc[3], ph4, vh[2], vh[3]);
            mma_bf16(oacc[3], pl4, vh[2], vh[3]);
            mma_bf16(oacc[3], ph4, vl[2], vl[3]);
        }
    }

    float inv_lo = 1.0f / *(float*)(sm + SL_O + r_lo * 4);
    float inv_hi = 1.0f / *(float*)(sm + SL_O + r_hi * 4);
#pragma unroll
    for (int nt = 0; nt < 4; nt++) {
        int d = 32 * wq + 8 * nt + (lane & 3) * 2;
        float* p0 = g_o + (size_t)(l0 + r_lo) * HID + h * DH + d;
        float* p1 = g_o + (size_t)(l0 + r_hi) * HID + h * DH + d;
        *(float2*)p0 = make_float2(oacc[nt][0] * inv_lo, oacc[nt][1] * inv_lo);
        *(float2*)p1 = make_float2(oacc[nt][2] * inv_hi, oacc[nt][3] * inv_hi);
    }
}

// ---------------- launch ----------------
extern "C" void kernel_launch(void* const* d_in, const int* in_sizes, int n_in,
                              void* d_out, int out_size) {
    const float* x     = (const float*)d_in[0];
    const float* xctx  = (const float*)d_in[1];
    const float* cosq  = (const float*)d_in[2];
    const float* sinq  = (const float*)d_in[3];
    const float* cosk  = (const float*)d_in[4];
    const float* sink  = (const float*)d_in[5];
    const float* cK    = (const float*)d_in[6];
    const float* cV    = (const float*)d_in[7];
    const float* Wq    = (const float*)d_in[9];
    const float* Wk    = (const float*)d_in[10];
    const float* Wv    = (const float*)d_in[11];
    const float* Wo    = (const float*)d_in[12];
    const float* qw    = (const float*)d_in[13];
    const float* kw    = (const float*)d_in[14];

    float* out  = (float*)d_out;
    float* kOut = out + (size_t)LQ * HID;
    float* vOut = kOut + (size_t)HKV * TT * DH;

    cudaFuncSetAttribute(gemm_bf3, cudaFuncAttributeMaxDynamicSharedMemorySize,
                         81920);
    cudaFuncSetAttribute(attn_mma, cudaFuncAttributeMaxDynamicSharedMemorySize,
                         ATTN_SMEM);

    __nv_bfloat16 *actH, *actL, *wqH, *wqL, *wkH, *wkL, *wvH, *wvL,
                  *woH, *woL, *goH, *goL, *qrH, *qrL, *kcH, *kcL, *vcH, *vcL;
    cudaGetSymbolAddress((void**)&actH, c_actH);
    cudaGetSymbolAddress((void**)&actL, c_actL);
    cudaGetSymbolAddress((void**)&wqH,  c_wqH);
    cudaGetSymbolAddress((void**)&wqL,  c_wqL);
    cudaGetSymbolAddress((void**)&wkH,  c_wkH);
    cudaGetSymbolAddress((void**)&wkL,  c_wkL);
    cudaGetSymbolAddress((void**)&wvH,  c_wvH);
    cudaGetSymbolAddress((void**)&wvL,  c_wvL);
    cudaGetSymbolAddress((void**)&woH,  c_woH);
    cudaGetSymbolAddress((void**)&woL,  c_woL);
    cudaGetSymbolAddress((void**)&goH,  c_goH);
    cudaGetSymbolAddress((void**)&goL,  c_goL);
    cudaGetSymbolAddress((void**)&qrH,  c_qrH);
    cudaGetSymbolAddress((void**)&qrL,  c_qrL);
    cudaGetSymbolAddress((void**)&kcH,  c_kcH);
    cudaGetSymbolAddress((void**)&kcL,  c_kcL);
    cudaGetSymbolAddress((void**)&vcH,  c_vcH);
    cudaGetSymbolAddress((void**)&vcL,  c_vcL);
    float *gq, *go;
    cudaGetSymbolAddress((void**)&gq, g_q);
    cudaGetSymbolAddress((void**)&go, g_o);
    float *gk, *gv;
    cudaGetSymbolAddress((void**)&gk, g_k);
    cudaGetSymbolAddress((void**)&gv, g_v);

    cache_split<<<(2 * CCH4 + 255) / 256, 256>>>(
        (const float4*)cK, (const float4*)cV,
        (uint2*)kcH, (uint2*)kcL, (uint2*)vcH, (uint2*)vcL);
    cvt_a<<<(ACT4 + 255) / 256, 256>>>((const float4*)xctx, (const float4*)x,
                                       (uint2*)actH, (uint2*)actL);
    {
        long long tot = 2LL * WQ4 + 2LL * WK4;
        cvt_w<<<(unsigned)((tot + 255) / 256), 256>>>(
            (const float4*)Wq, (const float4*)Wk, (const float4*)Wv,
            (const float4*)Wo,
            (uint2*)wqH, (uint2*)wqL, (uint2*)wkH, (uint2*)wkL,
            (uint2*)wvH, (uint2*)wvL, (uint2*)woH, (uint2*)woL);
    }
    gemm_bf3<<<dim3(64, 2, 1), 256, 81920>>>(
        actH + (size_t)CTXN * HID, actL + (size_t)CTXN * HID,
        wqH, wqL, wqH, wqL, gq, gq, HID);
    gemm_bf3<<<dim3(16, 16, 2), 256, 81920>>>(
        actH, actL, wkH, wkL, wvH, wvL, gk, gv, HKV * DH);
    qnorm_k<<<dim3(HQ, LQ), 128>>>(cosq, sinq, qw,
                                   (unsigned short*)qrH, qrL);
    kvnorm_k<<<dim3(HKV, TT), 128>>>(cosk, sink, kw, kOut, vOut,
                                     (unsigned short*)kcH, kcL,
                                     (unsigned short*)vcH, vcL);
    attn_mma<<<dim3(HQ, 4), 256, ATTN_SMEM>>>(qrH, qrL, kcH, kcL, vcH, vcL);
    cvt_go<<<(LQ * HID / 4 + 255) / 256, 256>>>((const float4*)go,
                                                (uint2*)goH, (uint2*)goL,
                                                LQ * HID / 4);
    gemm_bf3<<<dim3(64, 2, 1), 256, 81920>>>(
        goH, goL, woH, woL, woH, woL, out, out, HID);
}

// round 15
// speedup vs baseline: 1.8376x; 1.0067x over previous
#include <cuda_runtime.h>
#include <cuda_bf16.h>
#include <cstdint>
#include <cstddef>

#define HID   4096
#define LQ    128
#define CTXN  896
#define TT    1024
#define STATE 3072
#define HQ    32
#define HKV   8
#define DH    128
#define SCALE 0.08838834764831845f
#define NEPS  1e-6f

// ---------------- scratch (device globals; no allocation APIs) ----------------
__device__ __align__(16) float g_q [LQ * HID];
__device__ __align__(16) float g_k [TT * HKV * DH];   // also q/o-proj partial 0
__device__ __align__(16) float g_v [TT * HKV * DH];   // also q/o-proj partial 1
__device__ __align__(16) float g_o [LQ * HID];

// attention split-KV partials
__device__ __align__(16) float g_aO[2 * HQ * LQ * DH];
__device__ __align__(16) float g_aM[2 * HQ * LQ];
__device__ __align__(16) float g_aL[2 * HQ * LQ];

__device__ __align__(16) __nv_bfloat16 c_actH[TT * HID];
__device__ __align__(16) __nv_bfloat16 c_actL[TT * HID];
__device__ __align__(16) __nv_bfloat16 c_wqH [HID * HID];
__device__ __align__(16) __nv_bfloat16 c_wqL [HID * HID];
__device__ __align__(16) __nv_bfloat16 c_wkH [HKV * DH * HID];
__device__ __align__(16) __nv_bfloat16 c_wkL [HKV * DH * HID];
__device__ __align__(16) __nv_bfloat16 c_wvH [HKV * DH * HID];
__device__ __align__(16) __nv_bfloat16 c_wvL [HKV * DH * HID];
__device__ __align__(16) __nv_bfloat16 c_woH [HID * HID];
__device__ __align__(16) __nv_bfloat16 c_woL [HID * HID];
__device__ __align__(16) __nv_bfloat16 c_goH [LQ * HID];
__device__ __align__(16) __nv_bfloat16 c_goL [LQ * HID];

// attention operands, pre-split
__device__ __align__(16) __nv_bfloat16 c_qrH[HQ * LQ * DH];
__device__ __align__(16) __nv_bfloat16 c_qrL[HQ * LQ * DH];
__device__ __align__(16) __nv_bfloat16 c_kcH[HKV * 4096 * DH];
__device__ __align__(16) __nv_bfloat16 c_kcL[HKV * 4096 * DH];
__device__ __align__(16) __nv_bfloat16 c_vcH[HKV * 4096 * DH];
__device__ __align__(16) __nv_bfloat16 c_vcL[HKV * 4096 * DH];

// ---------------- mma helpers ----------------
static __device__ __forceinline__ uint32_t smem_u32(const void* p) {
    uint32_t a;
    asm("{ .reg .u64 t; cvta.to.shared.u64 t, %1; cvt.u32.u64 %0, t; }"
        : "=r"(a) : "l"(p));
    return a;
}
static __device__ __forceinline__ void ldm4(uint32_t* r, uint32_t addr) {
    asm volatile("ldmatrix.sync.aligned.m8n8.x4.shared.b16 {%0,%1,%2,%3}, [%4];"
                 : "=r"(r[0]), "=r"(r[1]), "=r"(r[2]), "=r"(r[3]) : "r"(addr));
}
static __device__ __forceinline__ void ldm4t(uint32_t* r, uint32_t addr) {
    asm volatile("ldmatrix.sync.aligned.m8n8.x4.trans.shared.b16 {%0,%1,%2,%3}, [%4];"
                 : "=r"(r[0]), "=r"(r[1]), "=r"(r[2]), "=r"(r[3]) : "r"(addr));
}
static __device__ __forceinline__ void mma_bf16(float* c, const uint32_t* a,
                                                uint32_t b0, uint32_t b1) {
    asm volatile(
        "mma.sync.aligned.m16n8k16.row.col.f32.bf16.bf16.f32 "
        "{%0,%1,%2,%3}, {%4,%5,%6,%7}, {%8,%9}, {%0,%1,%2,%3};"
        : "+f"(c[0]), "+f"(c[1]), "+f"(c[2]), "+f"(c[3])
        : "r"(a[0]), "r"(a[1]), "r"(a[2]), "r"(a[3]), "r"(b0), "r"(b1));
}
#define CPA16(dst, src) \
    asm volatile("cp.async.cg.shared.global [%0], [%1], 16;" \
                 :: "r"(dst), "l"(src) : "memory")
#define CPA_COMMIT() asm volatile("cp.async.commit_group;" ::: "memory")
#define CPA_WAIT2()  asm volatile("cp.async.wait_group 2;" ::: "memory")
#define CPA_WAIT0()  asm volatile("cp.async.wait_group 0;" ::: "memory")

// ---------------- fp32 -> (hi, lo) split core ----------------
static __device__ __forceinline__ void split4(float4 f, uint2& h, uint2& l) {
    uint32_t u0 = __float_as_uint(f.x), u1 = __float_as_uint(f.y);
    uint32_t u2 = __float_as_uint(f.z), u3 = __float_as_uint(f.w);
    h.x = __byte_perm(u0, u1, 0x7632);
    h.y = __byte_perm(u2, u3, 0x7632);
    float l0 = f.x - __uint_as_float(u0 & 0xFFFF0000u);
    float l1 = f.y - __uint_as_float(u1 & 0xFFFF0000u);
    float l2 = f.z - __uint_as_float(u2 & 0xFFFF0000u);
    float l3 = f.w - __uint_as_float(u3 & 0xFFFF0000u);
    __nv_bfloat162 p0 = __float22bfloat162_rn(make_float2(l0, l1));
    __nv_bfloat162 p1 = __float22bfloat162_rn(make_float2(l2, l3));
    l.x = *(uint32_t*)&p0;
    l.y = *(uint32_t*)&p1;
}

// acts: concat(xctx, x) -> c_act{H,L}
#define ACT4   (TT * HID / 4)
#define CTX4   (CTXN * HID / 4)
__global__ __launch_bounds__(256) void cvt_a(
    const float4* __restrict__ xctx, const float4* __restrict__ x,
    uint2* __restrict__ hi, uint2* __restrict__ lo)
{
    int i = blockIdx.x * 256 + threadIdx.x;
    if (i >= ACT4) return;
    float4 f = (i < CTX4) ? xctx[i] : x[i - CTX4];
    uint2 h, l; split4(f, h, l);
    hi[i] = h; lo[i] = l;
}

// weights: Wq | Wk | Wv | Wo
#define WQ4 (HID * HID / 4)
#define WK4 (HKV * DH * HID / 4)
__global__ __launch_bounds__(256) void cvt_w(
    const float4* __restrict__ wq, const float4* __restrict__ wk,
    const float4* __restrict__ wv, const float4* __restrict__ wo,
    uint2* __restrict__ qH, uint2* __restrict__ qL,
    uint2* __restrict__ kH, uint2* __restrict__ kL,
    uint2* __restrict__ vH, uint2* __restrict__ vL,
    uint2* __restrict__ oH, uint2* __restrict__ oL)
{
    long long i = (long long)blockIdx.x * 256 + threadIdx.x;
    const long long s0 = WQ4, s1 = s0 + WK4, s2 = s1 + WK4, s3 = s2 + WQ4;
    if (i >= s3) return;
    const float4* src; uint2 *dh, *dl; long long j;
    if      (i < s0) { src = wq; dh = qH; dl = qL; j = i; }
    else if (i < s1) { src = wk; dh = kH; dl = kL; j = i - s0; }
    else if (i < s2) { src = wv; dh = vH; dl = vL; j = i - s1; }
    else             { src = wo; dh = oH; dl = oL; j = i - s2; }
    uint2 h, l; split4(src[j], h, l);
    dh[j] = h; dl[j] = l;
}

__global__ __launch_bounds__(256) void cvt_go(
    const float4* __restrict__ src, uint2* __restrict__ hi,
    uint2* __restrict__ lo, int n4)
{
    int i = blockIdx.x * 256 + threadIdx.x;
    if (i >= n4) return;
    uint2 h, l; split4(src[i], h, l);
    hi[i] = h; lo[i] = l;
}

// cache region of kcat/vcat
#define CCH4 (HKV * STATE * DH / 4)
__global__ __launch_bounds__(256) void cache_split(
    const float4* __restrict__ cK, const float4* __restrict__ cV,
    uint2* __restrict__ kH, uint2* __restrict__ kL,
    uint2* __restrict__ vH, uint2* __restrict__ vL)
{
    int i = blockIdx.x * 256 + threadIdx.x;
    if (i >= 2 * CCH4) return;
    const float4* src = (i < CCH4) ? cK : cV;
    uint2 *dh = (i < CCH4) ? kH : vH;
    uint2 *dl = (i < CCH4) ? kL : vL;
    int j = (i < CCH4) ? i : i - CCH4;
    int e = j * 4;
    int g = e / (STATE * DH);
    int rem = e - g * (STATE * DH);
    int s = rem / DH;
    int d = rem - s * DH;
    uint2 h, l; split4(src[j], h, l);
    size_t dst = ((size_t)(g * 4096 + s) * DH + d) / 4;
    dh[dst] = h; dl[dst] = l;
}

// ---- elementwise add (split-K combine): o = a + b ----
__global__ __launch_bounds__(256) void add_k(
    const float4* __restrict__ a, const float4* __restrict__ b,
    float4* __restrict__ o, int n4)
{
    int i = blockIdx.x * 256 + threadIdx.x;
    if (i >= n4) return;
    float4 x = a[i], y = b[i];
    o[i] = make_float4(x.x + y.x, x.y + y.y, x.z + y.z, x.w + y.w);
}

// ============ GEMM: C[M,N] = A[M,K] * B[N,K]^T (pre-split bf16) ============
// koffz==0: z selects B/C pair (kv mode), K=4096.
// koffz>0 : split-K — koff = z*koffz, B fixed, C = z? C1 : C0, K = koffz.
#define GP       40
#define ARR_B    5120u
#define STG_B    20480u
__global__ __launch_bounds__(256) void gemm_bf3(
    const __nv_bfloat16* __restrict__ aH, const __nv_bfloat16* __restrict__ aL,
    const __nv_bfloat16* __restrict__ bH0, const __nv_bfloat16* __restrict__ bL0,
    const __nv_bfloat16* __restrict__ bH1, const __nv_bfloat16* __restrict__ bL1,
    float* __restrict__ C0, float* __restrict__ C1, int ldc, int koffz)
{
    extern __shared__ __align__(16) char sm[];
    const int tid  = threadIdx.x;
    const int lane = tid & 31;
    const int wid  = tid >> 5;
    const int wm   = wid >> 2;
    const int wn   = wid & 3;
    const int m0   = blockIdx.y * 64;
    const int n0   = blockIdx.x * 64;
    const int z    = blockIdx.z;

    const __nv_bfloat16 *bH, *bL; float* C; int NK, koff;
    if (koffz == 0) {
        bH = z ? bH1 : bH0; bL = z ? bL1 : bL0; C = z ? C1 : C0;
        NK = 128; koff = 0;
    } else {
        bH = bH0; bL = bL0; C = z ? C1 : C0;
        NK = koffz / 32; koff = z * koffz;
    }

    const int row = tid >> 2, c4 = tid & 3;
    const __nv_bfloat16* gaH = aH + (size_t)(m0 + row) * 4096 + koff + c4 * 8;
    const __nv_bfloat16* gaL = aL + (size_t)(m0 + row) * 4096 + koff + c4 * 8;
    const __nv_bfloat16* gbH = bH + (size_t)(n0 + row) * 4096 + koff + c4 * 8;
    const __nv_bfloat16* gbL = bL + (size_t)(n0 + row) * 4096 + koff + c4 * 8;

    const uint32_t smBase = smem_u32(sm);
    const uint32_t sOff   = (uint32_t)(row * 80 + c4 * 16);

    const int mrl = (lane & 7) + ((lane >> 3) & 1) * 8;
    const int kof = ((lane >> 4) & 1) * 8;
    const uint32_t aoff = (uint32_t)(((32 * wm + mrl) * GP + kof) * 2);
    const uint32_t boff = (uint32_t)(((16 * wn + mrl) * GP + kof) * 2);

    float acc[2][2][4];
#pragma unroll
    for (int i = 0; i < 2; i++)
#pragma unroll
        for (int j = 0; j < 2; j++)
#pragma unroll
            for (int e = 0; e < 4; e++) acc[i][j][e] = 0.0f;

#pragma unroll
    for (int p = 0; p < 3; p++) {
        uint32_t d = smBase + (uint32_t)p * STG_B + sOff;
        int k0 = p * 32;
        CPA16(d,             gaH + k0);
        CPA16(d + ARR_B,     gaL + k0);
        CPA16(d + 2 * ARR_B, gbH + k0);
        CPA16(d + 3 * ARR_B, gbL + k0);
        CPA_COMMIT();
    }

    for (int ic = 0; ic < NK; ic++) {
        CPA_WAIT2();
        __syncthreads();

        const uint32_t sb = smBase + (uint32_t)(ic & 3) * STG_B;
#pragma unroll
        for (int ks = 0; ks < 2; ks++) {
            const uint32_t kb = (uint32_t)ks * 32;
            uint32_t Ah[2][4], Al[2][4], Bh[4], Bl[4];
            ldm4(Ah[0], sb + aoff + kb);
            ldm4(Ah[1], sb + aoff + 16 * GP * 2 + kb);
            ldm4(Al[0], sb + ARR_B + aoff + kb);
            ldm4(Al[1], sb + ARR_B + aoff + 16 * GP * 2 + kb);
            ldm4(Bh,    sb + 2 * ARR_B + boff + kb);
            ldm4(Bl,    sb + 3 * ARR_B + boff + kb);
#pragma unroll
            for (int tm = 0; tm < 2; tm++)
#pragma unroll
                for (int tn = 0; tn < 2; tn++) {
                    mma_bf16(acc[tm][tn], Ah[tm], Bh[tn], Bh[tn + 2]);
                    mma_bf16(acc[tm][tn], Al[tm], Bh[tn], Bh[tn + 2]);
                    mma_bf16(acc[tm][tn], Ah[tm], Bl[tn], Bl[tn + 2]);
                }
        }

        if (ic + 3 < NK) {
            int k0 = (ic + 3) * 32;
            uint32_t d = smBase + (uint32_t)((ic + 3) & 3) * STG_B + sOff;
            CPA16(d,             gaH + k0);
            CPA16(d + ARR_B,     gaL + k0);
            CPA16(d + 2 * ARR_B, gbH + k0);
            CPA16(d + 3 * ARR_B, gbL + k0);
        }
        CPA_COMMIT();
    }

    const int r0 = m0 + 32 * wm + (lane >> 2);
    const int c0 = n0 + 16 * wn + (lane & 3) * 2;
#pragma unroll
    for (int tm = 0; tm < 2; tm++)
#pragma unroll
        for (int tn = 0; tn < 2; tn++) {
            float* p = C + (size_t)(r0 + 16 * tm) * ldc + c0 + 8 * tn;
            *(float2*)p = make_float2(acc[tm][tn][0], acc[tm][tn][1]);
            float* p2 = p + (size_t)8 * ldc;
            *(float2*)p2 = make_float2(acc[tm][tn][2], acc[tm][tn][3]);
        }
}

// ---------------- ane-norm + RoPE + scale for Q -> split bf16 ----------------
__global__ __launch_bounds__(128) void qnorm_k(
    const float* __restrict__ cq, const float* __restrict__ sq,
    const float* __restrict__ w,
    unsigned short* __restrict__ qrH, __nv_bfloat16* __restrict__ qrL)
{
    int h = blockIdx.x, l = blockIdx.y, d = threadIdx.x;
    __shared__ float red[8];
    __shared__ float xs[128];
    float v = g_q[l * HID + h * DH + d];
    float s1 = v, s2 = v * v;
#pragma unroll
    for (int off = 16; off; off >>= 1) {
        s1 += __shfl_down_sync(0xffffffffu, s1, off);
        s2 += __shfl_down_sync(0xffffffffu, s2, off);
    }
    if ((d & 31) == 0) { red[d >> 5] = s1; red[4 + (d >> 5)] = s2; }
    __syncthreads();
    float sum = red[0] + red[1] + red[2] + red[3];
    float sqs = red[4] + red[5] + red[6] + red[7];
    float mean = sum * (1.0f / 128.0f);
    float var  = sqs * (1.0f / 128.0f) - mean * mean;
    float xn = (v - mean) * rsqrtf(var + NEPS) * w[d];
    xs[d] = xn;
    __syncthreads();
    float rot = (d < 64) ? -xs[d + 64] : xs[d - 64];
    float o = (xn * cq[l * DH + d] + rot * sq[l * DH + d]) * SCALE;
    size_t idx = ((size_t)h * LQ + l) * DH + d;
    uint32_t u = __float_as_uint(o);
    qrH[idx] = (unsigned short)(u >> 16);
    qrL[idx] = __float2bfloat16_rn(o - __uint_as_float(u & 0xFFFF0000u));
}

// ---------- ane-norm + RoPE for K; outputs fp32 k/v + split kcat/vcat --------
__global__ __launch_bounds__(128) void kvnorm_k(
    const float* __restrict__ ck, const float* __restrict__ sk,
    const float* __restrict__ w,
    float* __restrict__ kOut, float* __restrict__ vOut,
    unsigned short* __restrict__ kcH, __nv_bfloat16* __restrict__ kcL,
    unsigned short* __restrict__ vcH, __nv_bfloat16* __restrict__ vcL)
{
    int h = blockIdx.x, t = blockIdx.y, d = threadIdx.x;
    __shared__ float red[8];
    __shared__ float xs[128];
    float v = g_k[t * (HKV * DH) + h * DH + d];
    float s1 = v, s2 = v * v;
#pragma unroll
    for (int off = 16; off; off >>= 1) {
        s1 += __shfl_down_sync(0xffffffffu, s1, off);
        s2 += __shfl_down_sync(0xffffffffu, s2, off);
    }
    if ((d & 31) == 0) { red[d >> 5] = s1; red[4 + (d >> 5)] = s2; }
    __syncthreads();
    float sum = red[0] + red[1] + red[2] + red[3];
    float sqs = red[4] + red[5] + red[6] + red[7];
    float mean = sum * (1.0f / 128.0f);
    float var  = sqs * (1.0f / 128.0f) - mean * mean;
    float xn = (v - mean) * rsqrtf(var + NEPS) * w[d];
    xs[d] = xn;
    __syncthreads();
    float rot = (d < 64) ? -xs[d + 64] : xs[d - 64];
    float kv = xn * ck[t * DH + d] + rot * sk[t * DH + d];
    float vv = g_v[t * (HKV * DH) + h * DH + d];
    kOut[((size_t)h * TT + t) * DH + d] = kv;
    vOut[((size_t)h * TT + t) * DH + d] = vv;
    size_t ci = ((size_t)h * 4096 + STATE + t) * DH + d;
    uint32_t uk = __float_as_uint(kv);
    kcH[ci] = (unsigned short)(uk >> 16);
    kcL[ci] = __float2bfloat16_rn(kv - __uint_as_float(uk & 0xFFFF0000u));
    uint32_t uv = __float_as_uint(vv);
    vcH[ci] = (unsigned short)(uv >> 16);
    vcL[ci] = __float2bfloat16_rn(vv - __uint_as_float(uv & 0xFFFF0000u));
}

// ============ Flash attention, split-KV=2, single-stage K/V buffer ==========
// CTA = (head, q-tile of 32, kv-split z). 256 thr, 8 warps. 2 CTAs/SM.
#define PQB 272u
#define PPB 144u
#define AQH_O 0u
#define AQL_O 8704u
#define ASTG  17408u          // Kh | Kl | Vh | Vl @ 17408 each -> ends 87040
#define ASS_O 87040u          // 32 x 272B scores
#define APH_O 95744u
#define APL_O 100352u
#define ASM_O 104960u
#define ASL_O 105088u
#define ASC_O 105216u
#define ATTN_SMEM 105344
__global__ __launch_bounds__(256) void attn_mma(
    const __nv_bfloat16* __restrict__ qrH, const __nv_bfloat16* __restrict__ qrL,
    const __nv_bfloat16* __restrict__ kcH, const __nv_bfloat16* __restrict__ kcL,
    const __nv_bfloat16* __restrict__ vcH, const __nv_bfloat16* __restrict__ vcL,
    float* __restrict__ pO, float* __restrict__ pM, float* __restrict__ pL)
{
    extern __shared__ __align__(16) char sm[];
    const uint32_t base = smem_u32(sm);
    const int tid  = threadIdx.x;
    const int lane = tid & 31;
    const int wid  = tid >> 5;
    const int mw   = wid & 1;
    const int wq   = wid >> 1;
    const int h  = blockIdx.x;
    const int qt = blockIdx.y;
    const int z  = blockIdx.z;
    const int g  = h >> 2;
    const int l0 = qt * 32;

    {
        int r = tid >> 3, c = (tid & 7) * 2;
        const uint4* gh = (const uint4*)(qrH + ((size_t)h * LQ + l0 + r) * DH) + c;
        const uint4* gl = (const uint4*)(qrL + ((size_t)h * LQ + l0 + r) * DH) + c;
        uint4* dh = (uint4*)(sm + AQH_O + r * PQB) + c;
        uint4* dl = (uint4*)(sm + AQL_O + r * PQB) + c;
        dh[0] = gh[0]; dh[1] = gh[1];
        dl[0] = gl[0]; dl[1] = gl[1];
    }
    if (tid < 32) {
        *(float*)(sm + ASM_O + tid * 4) = -1e30f;
        *(float*)(sm + ASL_O + tid * 4) = 0.0f;
    }

    const int fa = tid >> 6, fr = tid & 63;
    const __nv_bfloat16* farr =
        (fa == 0 ? kcH : fa == 1 ? kcL : fa == 2 ? vcH : vcL) +
        (size_t)(g * 4096 + fr) * DH;
    const uint32_t fdst = base + ASTG + (uint32_t)fa * 17408u + (uint32_t)fr * PQB;

    const int ntile = (3968 + l0 + 31) / 64 + 1;
    const int h0 = ntile >> 1;
    const int t0 = z ? h0 : 0;
    const int t1 = z ? ntile : h0;

    const uint32_t lmQ = (uint32_t)((16 * mw + (lane & 15)) * PQB + (lane >> 4) * 16);
    const uint32_t lmK = (uint32_t)((16 * wq + (lane & 15)) * PQB + (lane >> 4) * 16);
    const uint32_t lmP = (uint32_t)((16 * mw + (lane & 15)) * PPB + (lane >> 4) * 16);
    const uint32_t lmV = (uint32_t)((lane & 15) * PQB +
                                    (32 * wq + (lane >> 4) * 8) * 2);
    const int r_lo = 16 * mw + (lane >> 2);
    const int r_hi = r_lo + 8;
    const uint32_t sg = base + ASTG;

    float oacc[4][4];
#pragma unroll
    for (int i = 0; i < 4; i++)
#pragma unroll
        for (int e = 0; e < 4; e++) oacc[i][e] = 0.0f;

    for (int t = t0; t < t1; t++) {
        const int s0 = t * 64;

        __syncthreads();   // prev tile's K/V and P fully consumed
        {
            const __nv_bfloat16* src = farr + (size_t)t * 64 * DH;
#pragma unroll
            for (int c = 0; c < 16; c++) CPA16(fdst + c * 16, src + c * 8);
        }
        CPA_COMMIT();
        CPA_WAIT0();
        __syncthreads();   // K/V visible

        // ---- scores: S[32,64] = Q * K^T (3-term) ----
        float sacc[2][4];
#pragma unroll
        for (int i = 0; i < 2; i++)
#pragma unroll
            for (int e = 0; e < 4; e++) sacc[i][e] = 0.0f;
#pragma unroll
        for (int kt = 0; kt < 8; kt++) {
            uint32_t qh[4], ql[4], kh[4], kl[4];
            ldm4(qh, base + AQH_O + lmQ + kt * 32);
            ldm4(ql, base + AQL_O + lmQ + kt * 32);
            ldm4(kh, sg + lmK + kt * 32);
            ldm4(kl, sg + 17408u + lmK + kt * 32);
#pragma unroll
            for (int nt = 0; nt < 2; nt++) {
                mma_bf16(sacc[nt], qh, kh[nt], kh[nt + 2]);
                mma_bf16(sacc[nt], ql, kh[nt], kh[nt + 2]);
                mma_bf16(sacc[nt], qh, kl[nt], kl[nt + 2]);
            }
        }
        {
            int lim_lo = 3968 + l0 + r_lo;
            int lim_hi = lim_lo + 8;
#pragma unroll
            for (int nt = 0; nt < 2; nt++) {
                int c0 = 16 * wq + 8 * nt + (lane & 3) * 2;
                int k0g = s0 + c0;
                float v0 = (k0g     <= lim_lo) ? sacc[nt][0] : -1e30f;
                float v1 = (k0g + 1 <= lim_lo) ? sacc[nt][1] : -1e30f;
                float v2 = (k0g     <= lim_hi) ? sacc[nt][2] : -1e30f;
                float v3 = (k0g + 1 <= lim_hi) ? sacc[nt][3] : -1e30f;
                *(float2*)(sm + ASS_O + r_lo * PQB + c0 * 4) = make_float2(v0, v1);
                *(float2*)(sm + ASS_O + r_hi * PQB + c0 * 4) = make_float2(v2, v3);
            }
        }
        __syncthreads();

        // ---- parallel online softmax: 8 threads per row ----
        {
            int r = tid >> 3, cg = tid & 7;
            float* row = (float*)(sm + ASS_O + r * PQB);
            float4 a = ((float4*)row)[cg * 2];
            float4 b = ((float4*)row)[cg * 2 + 1];
            float mx = fmaxf(fmaxf(fmaxf(a.x, a.y), fmaxf(a.z, a.w)),
                             fmaxf(fmaxf(b.x, b.y), fmaxf(b.z, b.w)));
#pragma unroll
            for (int o = 1; o < 8; o <<= 1)
                mx = fmaxf(mx, __shfl_xor_sync(0xffffffffu, mx, o));
            float mOld = *(float*)(sm + ASM_O + r * 4);
            mx = fmaxf(mx, mOld);
            float e[8];
            e[0] = __expf(a.x - mx); e[1] = __expf(a.y - mx);
            e[2] = __expf(a.z - mx); e[3] = __expf(a.w - mx);
            e[4] = __expf(b.x - mx); e[5] = __expf(b.y - mx);
            e[6] = __expf(b.z - mx); e[7] = __expf(b.w - mx);
            float s = ((e[0] + e[1]) + (e[2] + e[3])) +
                      ((e[4] + e[5]) + (e[6] + e[7]));
#pragma unroll
            for (int o = 1; o < 8; o <<= 1)
                s += __shfl_xor_sync(0xffffffffu, s, o);
            uint32_t* ph = (uint32_t*)(sm + APH_O + r * PPB) + cg * 4;
            uint32_t* pl = (uint32_t*)(sm + APL_O + r * PPB) + cg * 4;
#pragma unroll
            for (int j = 0; j < 4; j++) {
                uint32_t u0 = __float_as_uint(e[2 * j]);
                uint32_t u1 = __float_as_uint(e[2 * j + 1]);
                ph[j] = __byte_perm(u0, u1, 0x7632);
                float f0 = e[2 * j]     - __uint_as_float(u0 & 0xFFFF0000u);
                float f1 = e[2 * j + 1] - __uint_as_float(u1 & 0xFFFF0000u);
                __nv_bfloat162 p = __float22bfloat162_rn(make_float2(f0, f1));
                pl[j] = *(uint32_t*)&p;
            }
            if (cg == 0) {
                float c = __expf(mOld - mx);
                *(float*)(sm + ASM_O + r * 4) = mx;
                *(float*)(sm + ASL_O + r * 4) =
                    *(float*)(sm + ASL_O + r * 4) * c + s;
                *(float*)(sm + ASC_O + r * 4) = c;
            }
        }
        __syncthreads();

        // ---- PV: O[32,128] += P[32,64] * V[64,128] (3-term) ----
        {
            float c_lo = *(float*)(sm + ASC_O + r_lo * 4);
            float c_hi = *(float*)(sm + ASC_O + r_hi * 4);
#pragma unroll
            for (int nt = 0; nt < 4; nt++) {
                oacc[nt][0] *= c_lo; oacc[nt][1] *= c_lo;
                oacc[nt][2] *= c_hi; oacc[nt][3] *= c_hi;
            }
        }
        const uint32_t vgh = sg + 34816u;
        const uint32_t vgl = sg + 52224u;
#pragma unroll
        for (int kt = 0; kt < 4; kt++) {
            uint32_t ph4[4], pl4[4];
            ldm4(ph4, base + APH_O + lmP + kt * 32);
            ldm4(pl4, base + APL_O + lmP + kt * 32);
            uint32_t vrow = (uint32_t)(16 * kt) * PQB + lmV;
            uint32_t vh[4], vl[4];
            ldm4t(vh, vgh + vrow);
            ldm4t(vl, vgl + vrow);
            mma_bf16(oacc[0], ph4, vh[0], vh[1]);
            mma_bf16(oacc[0], pl4, vh[0], vh[1]);
            mma_bf16(oacc[0], ph4, vl[0], vl[1]);
            mma_bf16(oacc[1], ph4, vh[2], vh[3]);
            mma_bf16(oacc[1], pl4, vh[2], vh[3]);
            mma_bf16(oacc[1], ph4, vl[2], vl[3]);
            uint32_t vrow2 = vrow + 32;
            ldm4t(vh, vgh + vrow2);
            ldm4t(vl, vgl + vrow2);
            mma_bf16(oacc[2], ph4, vh[0], vh[1]);
            mma_bf16(oacc[2], pl4, vh[0], vh[1]);
            mma_bf16(oacc[2], ph4, vl[0], vl[1]);
            mma_bf16(oacc[3], ph4, vh[2], vh[3]);
            mma_bf16(oacc[3], pl4, vh[2], vh[3]);
            mma_bf16(oacc[3], ph4, vl[2], vl[3]);
        }
    }

    // ---- write unnormalized partial O, plus m and l ----
    float* oBase = pO + ((size_t)(z * HQ + h) * LQ) * DH;
#pragma unroll
    for (int nt = 0; nt < 4; nt++) {
        int d = 32 * wq + 8 * nt + (lane & 3) * 2;
        *(float2*)(oBase + (size_t)(l0 + r_lo) * DH + d) =
            make_float2(oacc[nt][0], oacc[nt][1]);
        *(float2*)(oBase + (size_t)(l0 + r_hi) * DH + d) =
            make_float2(oacc[nt][2], oacc[nt][3]);
    }
    if (tid < 32) {
        size_t mi = (size_t)(z * HQ + h) * LQ + l0 + tid;
        pM[mi] = *(float*)(sm + ASM_O + tid * 4);
        pL[mi] = *(float*)(sm + ASL_O + tid * 4);
    }
}

// ---- combine the two kv-splits -> g_o ----
__global__ __launch_bounds__(128) void attn_combine(
    const float* __restrict__ pO, const float* __restrict__ pM,
    const float* __restrict__ pL)
{
    int h = blockIdx.x, l = blockIdx.y, d = threadIdx.x;
    size_t i0 = (size_t)h * LQ + l;
    size_t i1 = (size_t)(HQ + h) * LQ + l;
    float m0 = pM[i0], m1 = pM[i1];
    float l0v = pL[i0], l1v = pL[i1];
    float m = fmaxf(m0, m1);
    float e0 = __expf(m0 - m), e1 = __expf(m1 - m);
    float inv = 1.0f / (e0 * l0v + e1 * l1v);
    float o0 = pO[(i0 * DH) + d];
    float o1 = pO[(i1 * DH) + d];
    g_o[(size_t)l * HID + h * DH + d] = (e0 * o0 + e1 * o1) * inv;
}

// ---------------- launch ----------------
extern "C" void kernel_launch(void* const* d_in, const int* in_sizes, int n_in,
                              void* d_out, int out_size) {
    const float* x     = (const float*)d_in[0];
    const float* xctx  = (const float*)d_in[1];
    const float* cosq  = (const float*)d_in[2];
    const float* sinq  = (const float*)d_in[3];
    const float* cosk  = (const float*)d_in[4];
    const float* sink  = (const float*)d_in[5];
    const float* cK    = (const float*)d_in[6];
    const float* cV    = (const float*)d_in[7];
    const float* Wq    = (const float*)d_in[9];
    const float* Wk    = (const float*)d_in[10];
    const float* Wv    = (const float*)d_in[11];
    const float* Wo    = (const float*)d_in[12];
    const float* qw    = (const float*)d_in[13];
    const float* kw    = (const float*)d_in[14];

    float* out  = (float*)d_out;
    float* kOut = out + (size_t)LQ * HID;
    float* vOut = kOut + (size_t)HKV * TT * DH;

    cudaFuncSetAttribute(gemm_bf3, cudaFuncAttributeMaxDynamicSharedMemorySize,
                         81920);
    cudaFuncSetAttribute(attn_mma, cudaFuncAttributeMaxDynamicSharedMemorySize,
                         ATTN_SMEM);

    __nv_bfloat16 *actH, *actL, *wqH, *wqL, *wkH, *wkL, *wvH, *wvL,
                  *woH, *woL, *goH, *goL, *qrH, *qrL, *kcH, *kcL, *vcH, *vcL;
    cudaGetSymbolAddress((void**)&actH, c_actH);
    cudaGetSymbolAddress((void**)&actL, c_actL);
    cudaGetSymbolAddress((void**)&wqH,  c_wqH);
    cudaGetSymbolAddress((void**)&wqL,  c_wqL);
    cudaGetSymbolAddress((void**)&wkH,  c_wkH);
    cudaGetSymbolAddress((void**)&wkL,  c_wkL);
    cudaGetSymbolAddress((void**)&wvH,  c_wvH);
    cudaGetSymbolAddress((void**)&wvL,  c_wvL);
    cudaGetSymbolAddress((void**)&woH,  c_woH);
    cudaGetSymbolAddress((void**)&woL,  c_woL);
    cudaGetSymbolAddress((void**)&goH,  c_goH);
    cudaGetSymbolAddress((void**)&goL,  c_goL);
    cudaGetSymbolAddress((void**)&qrH,  c_qrH);
    cudaGetSymbolAddress((void**)&qrL,  c_qrL);
    cudaGetSymbolAddress((void**)&kcH,  c_kcH);
    cudaGetSymbolAddress((void**)&kcL,  c_kcL);
    cudaGetSymbolAddress((void**)&vcH,  c_vcH);
    cudaGetSymbolAddress((void**)&vcL,  c_vcL);
    float *gq, *go, *gk, *gv, *aO, *aM, *aL;
    cudaGetSymbolAddress((void**)&gq, g_q);
    cudaGetSymbolAddress((void**)&go, g_o);
    cudaGetSymbolAddress((void**)&gk, g_k);
    cudaGetSymbolAddress((void**)&gv, g_v);
    cudaGetSymbolAddress((void**)&aO, g_aO);
    cudaGetSymbolAddress((void**)&aM, g_aM);
    cudaGetSymbolAddress((void**)&aL, g_aL);

    cache_split<<<(2 * CCH4 + 255) / 256, 256>>>(
        (const float4*)cK, (const float4*)cV,
        (uint2*)kcH, (uint2*)kcL, (uint2*)vcH, (uint2*)vcL);
    cvt_a<<<(ACT4 + 255) / 256, 256>>>((const float4*)xctx, (const float4*)x,
                                       (uint2*)actH, (uint2*)actL);
    {
        long long tot = 2LL * WQ4 + 2LL * WK4;
        cvt_w<<<(unsigned)((tot + 255) / 256), 256>>>(
            (const float4*)Wq, (const float4*)Wk, (const float4*)Wv,
            (const float4*)Wo,
            (uint2*)wqH, (uint2*)wqL, (uint2*)wkH, (uint2*)wkL,
            (uint2*)wvH, (uint2*)wvL, (uint2*)woH, (uint2*)woL);
    }
    // q projection: split-K=2, partials in g_k/g_v, then add -> g_q
    gemm_bf3<<<dim3(64, 2, 2), 256, 81920>>>(
        actH + (size_t)CTXN * HID, actL + (size_t)CTXN * HID,
        wqH, wqL, wqH, wqL, gk, gv, HID, 2048);
    add_k<<<(LQ * HID / 4 + 255) / 256, 256>>>(
        (const float4*)gk, (const float4*)gv, (float4*)gq, LQ * HID / 4);
    // k/v projection (overwrites g_k/g_v)
    gemm_bf3<<<dim3(16, 16, 2), 256, 81920>>>(
        actH, actL, wkH, wkL, wvH, wvL, gk, gv, HKV * DH, 0);
    qnorm_k<<<dim3(HQ, LQ), 128>>>(cosq, sinq, qw,
                                   (unsigned short*)qrH, qrL);
    kvnorm_k<<<dim3(HKV, TT), 128>>>(cosk, sink, kw, kOut, vOut,
                                     (unsigned short*)kcH, kcL,
                                     (unsigned short*)vcH, vcL);
    // attention: split-KV=2 + combine
    attn_mma<<<dim3(HQ, 4, 2), 256, ATTN_SMEM>>>(qrH, qrL, kcH, kcL, vcH, vcL,
                                                 aO, aM, aL);
    attn_combine<<<dim3(HQ, LQ), 128>>>(aO, aM, aL);
    // output projection: split-K=2, partials in g_k/g_v, then add -> out
    cvt_go<<<(LQ * HID / 4 + 255) / 256, 256>>>((const float4*)go,
                                                (uint2*)goH, (uint2*)goL,
                                                LQ * HID / 4);
    gemm_bf3<<<dim3(64, 2, 2), 256, 81920>>>(
        goH, goL, woH, woL, woH, woL, gk, gv, HID, 2048);
    add_k<<<(LQ * HID / 4 + 255) / 256, 256>>>(
        (const float4*)gk, (const float4*)gv, (float4*)out, LQ * HID / 4);
}

// round 16
// speedup vs baseline: 2.6889x; 1.4633x over previous
#include <cuda_runtime.h>
#include <cuda_fp16.h>
#include <cstdint>
#include <cstddef>

#define HID   4096
#define LQ    128
#define CTXN  896
#define TT    1024
#define STATE 3072
#define HQ    32
#define HKV   8
#define DH    128
#define SCALE 0.08838834764831845f
#define NEPS  1e-6f

// ---------------- scratch (device globals; no allocation APIs) ----------------
__device__ __align__(16) float g_q [LQ * HID];
__device__ __align__(16) float g_k [TT * HKV * DH];   // also q/o-proj partial 0
__device__ __align__(16) float g_v [TT * HKV * DH];   // also q/o-proj partial 1
__device__ __align__(16) float g_o [LQ * HID];

// attention split-KV partials
__device__ __align__(16) float g_aO[2 * HQ * LQ * DH];
__device__ __align__(16) float g_aM[2 * HQ * LQ];
__device__ __align__(16) float g_aL[2 * HQ * LQ];

// fp16 operands
__device__ __align__(16) __half c_actH[TT * HID];
__device__ __align__(16) __half c_actL[TT * HID];
__device__ __align__(16) __half c_wq  [HID * HID];
__device__ __align__(16) __half c_wk  [HKV * DH * HID];
__device__ __align__(16) __half c_wv  [HKV * DH * HID];
__device__ __align__(16) __half c_wo  [HID * HID];
__device__ __align__(16) __half c_goH [LQ * HID];
__device__ __align__(16) __half c_goL [LQ * HID];
__device__ __align__(16) __half c_qrH [HQ * LQ * DH];
__device__ __align__(16) __half c_qrL [HQ * LQ * DH];
__device__ __align__(16) __half c_kc  [HKV * 4096 * DH];
__device__ __align__(16) __half c_vc  [HKV * 4096 * DH];

// ---------------- mma helpers ----------------
static __device__ __forceinline__ uint32_t smem_u32(const void* p) {
    uint32_t a;
    asm("{ .reg .u64 t; cvta.to.shared.u64 t, %1; cvt.u32.u64 %0, t; }"
        : "=r"(a) : "l"(p));
    return a;
}
static __device__ __forceinline__ void ldm4(uint32_t* r, uint32_t addr) {
    asm volatile("ldmatrix.sync.aligned.m8n8.x4.shared.b16 {%0,%1,%2,%3}, [%4];"
                 : "=r"(r[0]), "=r"(r[1]), "=r"(r[2]), "=r"(r[3]) : "r"(addr));
}
static __device__ __forceinline__ void ldm4t(uint32_t* r, uint32_t addr) {
    asm volatile("ldmatrix.sync.aligned.m8n8.x4.trans.shared.b16 {%0,%1,%2,%3}, [%4];"
                 : "=r"(r[0]), "=r"(r[1]), "=r"(r[2]), "=r"(r[3]) : "r"(addr));
}
static __device__ __forceinline__ void mma_f16(float* c, const uint32_t* a,
                                               uint32_t b0, uint32_t b1) {
    asm volatile(
        "mma.sync.aligned.m16n8k16.row.col.f32.f16.f16.f32 "
        "{%0,%1,%2,%3}, {%4,%5,%6,%7}, {%8,%9}, {%0,%1,%2,%3};"
        : "+f"(c[0]), "+f"(c[1]), "+f"(c[2]), "+f"(c[3])
        : "r"(a[0]), "r"(a[1]), "r"(a[2]), "r"(a[3]), "r"(b0), "r"(b1));
}
#define CPA16(dst, src) \
    asm volatile("cp.async.cg.shared.global [%0], [%1], 16;" \
                 :: "r"(dst), "l"(src) : "memory")
#define CPA_COMMIT() asm volatile("cp.async.commit_group;" ::: "memory")
#define CPA_WAIT2()  asm volatile("cp.async.wait_group 2;" ::: "memory")
#define CPA_WAIT1G() asm volatile("cp.async.wait_group 1;" ::: "memory")

// ---------------- fp32 -> fp16 split helpers ----------------
static __device__ __forceinline__ void split4h(float4 f, uint2& h, uint2& l) {
    __half2 h01 = __floats2half2_rn(f.x, f.y);
    __half2 h23 = __floats2half2_rn(f.z, f.w);
    float2 r01 = __half22float2(h01);
    float2 r23 = __half22float2(h23);
    __half2 l01 = __floats2half2_rn(f.x - r01.x, f.y - r01.y);
    __half2 l23 = __floats2half2_rn(f.z - r23.x, f.w - r23.y);
    h.x = *(uint32_t*)&h01; h.y = *(uint32_t*)&h23;
    l.x = *(uint32_t*)&l01; l.y = *(uint32_t*)&l23;
}
static __device__ __forceinline__ uint2 cvt4h(float4 f) {
    __half2 h01 = __floats2half2_rn(f.x, f.y);
    __half2 h23 = __floats2half2_rn(f.z, f.w);
    uint2 h;
    h.x = *(uint32_t*)&h01; h.y = *(uint32_t*)&h23;
    return h;
}

// acts: concat(xctx, x) -> 2-split fp16
#define ACT4   (TT * HID / 4)
#define CTX4   (CTXN * HID / 4)
__global__ __launch_bounds__(256) void cvt_a(
    const float4* __restrict__ xctx, const float4* __restrict__ x,
    uint2* __restrict__ hi, uint2* __restrict__ lo)
{
    int i = blockIdx.x * 256 + threadIdx.x;
    if (i >= ACT4) return;
    float4 f = (i < CTX4) ? xctx[i] : x[i - CTX4];
    uint2 h, l; split4h(f, h, l);
    hi[i] = h; lo[i] = l;
}

// weights -> single rn fp16
#define WQ4 (HID * HID / 4)
#define WK4 (HKV * DH * HID / 4)
__global__ __launch_bounds__(256) void cvt_w(
    const float4* __restrict__ wq, const float4* __restrict__ wk,
    const float4* __restrict__ wv, const float4* __restrict__ wo,
    uint2* __restrict__ oq, uint2* __restrict__ ok,
    uint2* __restrict__ ov, uint2* __restrict__ oo)
{
    long long i = (long long)blockIdx.x * 256 + threadIdx.x;
    const long long s0 = WQ4, s1 = s0 + WK4, s2 = s1 + WK4, s3 = s2 + WQ4;
    if (i >= s3) return;
    const float4* src; uint2* dst; long long j;
    if      (i < s0) { src = wq; dst = oq; j = i; }
    else if (i < s1) { src = wk; dst = ok; j = i - s0; }
    else if (i < s2) { src = wv; dst = ov; j = i - s1; }
    else             { src = wo; dst = oo; j = i - s2; }
    dst[j] = cvt4h(src[j]);
}

__global__ __launch_bounds__(256) void cvt_go(
    const float4* __restrict__ src, uint2* __restrict__ hi,
    uint2* __restrict__ lo, int n4)
{
    int i = blockIdx.x * 256 + threadIdx.x;
    if (i >= n4) return;
    uint2 h, l; split4h(src[i], h, l);
    hi[i] = h; lo[i] = l;
}

// cache region of kc/vc: single rn fp16, pitch-4096 rows
#define CCH4 (HKV * STATE * DH / 4)
__global__ __launch_bounds__(256) void cache_split(
    const float4* __restrict__ cK, const float4* __restrict__ cV,
    uint2* __restrict__ kc, uint2* __restrict__ vc)
{
    int i = blockIdx.x * 256 + threadIdx.x;
    if (i >= 2 * CCH4) return;
    const float4* src = (i < CCH4) ? cK : cV;
    uint2* dst = (i < CCH4) ? kc : vc;
    int j = (i < CCH4) ? i : i - CCH4;
    int e = j * 4;
    int g = e / (STATE * DH);
    int rem = e - g * (STATE * DH);
    int s = rem / DH;
    int d = rem - s * DH;
    size_t di = ((size_t)(g * 4096 + s) * DH + d) / 4;
    dst[di] = cvt4h(src[j]);
}

// ---- elementwise add (split-K combine) ----
__global__ __launch_bounds__(256) void add_k(
    const float4* __restrict__ a, const float4* __restrict__ b,
    float4* __restrict__ o, int n4)
{
    int i = blockIdx.x * 256 + threadIdx.x;
    if (i >= n4) return;
    float4 x = a[i], y = b[i];
    o[i] = make_float4(x.x + y.x, x.y + y.y, x.z + y.z, x.w + y.w);
}

// ============ GEMM: C[M,N] = (Ah+Al)[M,K] * Bh[N,K]^T (fp16, 2 mma) ========
#define GP       40
#define ARR_B    5120u
#define STG_B    15360u     // Ah | Al | Bh
__global__ __launch_bounds__(256) void gemm_f16(
    const __half* __restrict__ aH, const __half* __restrict__ aL,
    const __half* __restrict__ bA, const __half* __restrict__ bB,
    float* __restrict__ C0, float* __restrict__ C1, int ldc, int koffz)
{
    extern __shared__ __align__(16) char sm[];
    const int tid  = threadIdx.x;
    const int lane = tid & 31;
    const int wid  = tid >> 5;
    const int wm   = wid >> 2;
    const int wn   = wid & 3;
    const int m0   = blockIdx.y * 64;
    const int n0   = blockIdx.x * 64;
    const int z    = blockIdx.z;

    const __half* bH; float* C; int NK, koff;
    if (koffz == 0) {
        bH = z ? bB : bA; C = z ? C1 : C0;
        NK = 128; koff = 0;
    } else {
        bH = bA; C = z ? C1 : C0;
        NK = koffz / 32; koff = z * koffz;
    }

    const int row = tid >> 2, c4 = tid & 3;
    const __half* gaH = aH + (size_t)(m0 + row) * 4096 + koff + c4 * 8;
    const __half* gaL = aL + (size_t)(m0 + row) * 4096 + koff + c4 * 8;
    const __half* gbH = bH + (size_t)(n0 + row) * 4096 + koff + c4 * 8;

    const uint32_t smBase = smem_u32(sm);
    const uint32_t sOff   = (uint32_t)(row * 80 + c4 * 16);

    const int mrl = (lane & 7) + ((lane >> 3) & 1) * 8;
    const int kof = ((lane >> 4) & 1) * 8;
    const uint32_t aoff = (uint32_t)(((32 * wm + mrl) * GP + kof) * 2);
    const uint32_t boff = (uint32_t)(((16 * wn + mrl) * GP + kof) * 2);

    float acc[2][2][4];
#pragma unroll
    for (int i = 0; i < 2; i++)
#pragma unroll
        for (int j = 0; j < 2; j++)
#pragma unroll
            for (int e = 0; e < 4; e++) acc[i][j][e] = 0.0f;

#pragma unroll
    for (int p = 0; p < 3; p++) {
        uint32_t d = smBase + (uint32_t)p * STG_B + sOff;
        int k0 = p * 32;
        CPA16(d,             gaH + k0);
        CPA16(d + ARR_B,     gaL + k0);
        CPA16(d + 2 * ARR_B, gbH + k0);
        CPA_COMMIT();
    }

    for (int ic = 0; ic < NK; ic++) {
        CPA_WAIT2();
        __syncthreads();

        const uint32_t sb = smBase + (uint32_t)(ic & 3) * STG_B;
#pragma unroll
        for (int ks = 0; ks < 2; ks++) {
            const uint32_t kb = (uint32_t)ks * 32;
            uint32_t Ah[2][4], Al[2][4], Bh[4];
            ldm4(Ah[0], sb + aoff + kb);
            ldm4(Ah[1], sb + aoff + 16 * GP * 2 + kb);
            ldm4(Al[0], sb + ARR_B + aoff + kb);
            ldm4(Al[1], sb + ARR_B + aoff + 16 * GP * 2 + kb);
            ldm4(Bh,    sb + 2 * ARR_B + boff + kb);
#pragma unroll
            for (int tm = 0; tm < 2; tm++)
#pragma unroll
                for (int tn = 0; tn < 2; tn++) {
                    mma_f16(acc[tm][tn], Ah[tm], Bh[tn], Bh[tn + 2]);
                    mma_f16(acc[tm][tn], Al[tm], Bh[tn], Bh[tn + 2]);
                }
        }

        if (ic + 3 < NK) {
            int k0 = (ic + 3) * 32;
            uint32_t d = smBase + (uint32_t)((ic + 3) & 3) * STG_B + sOff;
            CPA16(d,             gaH + k0);
            CPA16(d + ARR_B,     gaL + k0);
            CPA16(d + 2 * ARR_B, gbH + k0);
        }
        CPA_COMMIT();
    }

    const int r0 = m0 + 32 * wm + (lane >> 2);
    const int c0 = n0 + 16 * wn + (lane & 3) * 2;
#pragma unroll
    for (int tm = 0; tm < 2; tm++)
#pragma unroll
        for (int tn = 0; tn < 2; tn++) {
            float* p = C + (size_t)(r0 + 16 * tm) * ldc + c0 + 8 * tn;
            *(float2*)p = make_float2(acc[tm][tn][0], acc[tm][tn][1]);
            float* p2 = p + (size_t)8 * ldc;
            *(float2*)p2 = make_float2(acc[tm][tn][2], acc[tm][tn][3]);
        }
}

// ---------------- ane-norm + RoPE + scale for Q -> 2-split fp16 --------------
__global__ __launch_bounds__(128) void qnorm_k(
    const float* __restrict__ cq, const float* __restrict__ sq,
    const float* __restrict__ w,
    __half* __restrict__ qrH, __half* __restrict__ qrL)
{
    int h = blockIdx.x, l = blockIdx.y, d = threadIdx.x;
    __shared__ float red[8];
    __shared__ float xs[128];
    float v = g_q[l * HID + h * DH + d];
    float s1 = v, s2 = v * v;
#pragma unroll
    for (int off = 16; off; off >>= 1) {
        s1 += __shfl_down_sync(0xffffffffu, s1, off);
        s2 += __shfl_down_sync(0xffffffffu, s2, off);
    }
    if ((d & 31) == 0) { red[d >> 5] = s1; red[4 + (d >> 5)] = s2; }
    __syncthreads();
    float sum = red[0] + red[1] + red[2] + red[3];
    float sqs = red[4] + red[5] + red[6] + red[7];
    float mean = sum * (1.0f / 128.0f);
    float var  = sqs * (1.0f / 128.0f) - mean * mean;
    float xn = (v - mean) * rsqrtf(var + NEPS) * w[d];
    xs[d] = xn;
    __syncthreads();
    float rot = (d < 64) ? -xs[d + 64] : xs[d - 64];
    float o = (xn * cq[l * DH + d] + rot * sq[l * DH + d]) * SCALE;
    size_t idx = ((size_t)h * LQ + l) * DH + d;
    __half hh = __float2half_rn(o);
    qrH[idx] = hh;
    qrL[idx] = __float2half_rn(o - __half2float(hh));
}

// ---------- ane-norm + RoPE for K; fp32 k/v out + single-fp16 kc/vc ----------
__global__ __launch_bounds__(128) void kvnorm_k(
    const float* __restrict__ ck, const float* __restrict__ sk,
    const float* __restrict__ w,
    float* __restrict__ kOut, float* __restrict__ vOut,
    __half* __restrict__ kc, __half* __restrict__ vc)
{
    int h = blockIdx.x, t = blockIdx.y, d = threadIdx.x;
    __shared__ float red[8];
    __shared__ float xs[128];
    float v = g_k[t * (HKV * DH) + h * DH + d];
    float s1 = v, s2 = v * v;
#pragma unroll
    for (int off = 16; off; off >>= 1) {
        s1 += __shfl_down_sync(0xffffffffu, s1, off);
        s2 += __shfl_down_sync(0xffffffffu, s2, off);
    }
    if ((d & 31) == 0) { red[d >> 5] = s1; red[4 + (d >> 5)] = s2; }
    __syncthreads();
    float sum = red[0] + red[1] + red[2] + red[3];
    float sqs = red[4] + red[5] + red[6] + red[7];
    float mean = sum * (1.0f / 128.0f);
    float var  = sqs * (1.0f / 128.0f) - mean * mean;
    float xn = (v - mean) * rsqrtf(var + NEPS) * w[d];
    xs[d] = xn;
    __syncthreads();
    float rot = (d < 64) ? -xs[d + 64] : xs[d - 64];
    float kv = xn * ck[t * DH + d] + rot * sk[t * DH + d];
    float vv = g_v[t * (HKV * DH) + h * DH + d];
    kOut[((size_t)h * TT + t) * DH + d] = kv;
    vOut[((size_t)h * TT + t) * DH + d] = vv;
    size_t ci = ((size_t)h * 4096 + STATE + t) * DH + d;
    kc[ci] = __float2half_rn(kv);
    vc[ci] = __float2half_rn(vv);
}

// ===== Flash attention: fp16, 2-mma scores / 1-mma PV, split-KV=2 ==========
// CTA = (head, q-tile 32, kv-split). 256 thr. K/V double-buffered.
#define PQB 272u
#define PPB 144u
#define AQH_O 0u
#define AQL_O 8704u
#define ASTG  17408u         // stages: K(17408) | V(17408); 2 stages
#define STGSZ 34816u
#define ASS_O 87040u         // 17408 + 2*34816
#define APH_O 95744u         // P single: 32 x 144B
#define ASM_O 100352u
#define ASL_O 100480u
#define ASC_O 100608u
#define ATTN_SMEM 100736
__global__ __launch_bounds__(256) void attn_mma(
    const __half* __restrict__ qrH, const __half* __restrict__ qrL,
    const __half* __restrict__ kc, const __half* __restrict__ vc,
    float* __restrict__ pO, float* __restrict__ pM, float* __restrict__ pL)
{
    extern __shared__ __align__(16) char sm[];
    const uint32_t base = smem_u32(sm);
    const int tid  = threadIdx.x;
    const int lane = tid & 31;
    const int wid  = tid >> 5;
    const int mw   = wid & 1;
    const int wq   = wid >> 1;
    const int h  = blockIdx.x;
    const int qt = blockIdx.y;
    const int z  = blockIdx.z;
    const int g  = h >> 2;
    const int l0 = qt * 32;

    {
        int r = tid >> 3, c = (tid & 7) * 2;
        const uint4* gh = (const uint4*)(qrH + ((size_t)h * LQ + l0 + r) * DH) + c;
        const uint4* gl = (const uint4*)(qrL + ((size_t)h * LQ + l0 + r) * DH) + c;
        uint4* dh = (uint4*)(sm + AQH_O + r * PQB) + c;
        uint4* dl = (uint4*)(sm + AQL_O + r * PQB) + c;
        dh[0] = gh[0]; dh[1] = gh[1];
        dl[0] = gl[0]; dl[1] = gl[1];
    }
    if (tid < 32) {
        *(float*)(sm + ASM_O + tid * 4) = -1e30f;
        *(float*)(sm + ASL_O + tid * 4) = 0.0f;
    }

    // fill mapping: fa = K/V, r = row, hf = half-row (128B each)
    const int fa = tid >> 7, fr = (tid >> 1) & 63, hf = tid & 1;
    const __half* farr = (fa ? vc : kc) + (size_t)(g * 4096 + fr) * DH + hf * 64;
    const uint32_t fdst = base + ASTG + (uint32_t)fa * 17408u +
                          (uint32_t)fr * PQB + (uint32_t)hf * 128u;

    const int ntile = (3968 + l0 + 31) / 64 + 1;
    const int half0 = ntile >> 1;
    const int t0 = z ? half0 : 0;
    const int t1 = z ? ntile : half0;

    // prologue: fill stage 0 with tile t0
    {
        const __half* src = farr + (size_t)t0 * 64 * DH;
#pragma unroll
        for (int c = 0; c < 8; c++) CPA16(fdst + c * 16, src + c * 8);
        CPA_COMMIT();
    }

    const uint32_t lmQ = (uint32_t)((16 * mw + (lane & 15)) * PQB + (lane >> 4) * 16);
    const uint32_t lmK = (uint32_t)((16 * wq + (lane & 15)) * PQB + (lane >> 4) * 16);
    const uint32_t lmP = (uint32_t)((16 * mw + (lane & 15)) * PPB + (lane >> 4) * 16);
    const uint32_t lmV = (uint32_t)((lane & 15) * PQB +
                                    (32 * wq + (lane >> 4) * 8) * 2);
    const int r_lo = 16 * mw + (lane >> 2);
    const int r_hi = r_lo + 8;

    float oacc[4][4];
#pragma unroll
    for (int i = 0; i < 4; i++)
#pragma unroll
        for (int e = 0; e < 4; e++) oacc[i][e] = 0.0f;

    for (int t = t0; t < t1; t++) {
        const int tt = t - t0;
        const int st = tt & 1;
        const int s0 = t * 64;
        const uint32_t sg = base + ASTG + (uint32_t)st * STGSZ;

        __syncthreads();   // buffer st^1 (tile t-1) fully consumed
        if (t + 1 < t1) {
            const __half* src = farr + (size_t)(t + 1) * 64 * DH;
            const uint32_t d2 = fdst + (uint32_t)(st ^ 1) * STGSZ;
#pragma unroll
            for (int c = 0; c < 8; c++) CPA16(d2 + c * 16, src + c * 8);
        }
        CPA_COMMIT();
        CPA_WAIT1G();      // stage st landed
        __syncthreads();

        // ---- scores: S = (Qh+Ql) * K^T  (2 mma per n-tile) ----
        float sacc[2][4];
#pragma unroll
        for (int i = 0; i < 2; i++)
#pragma unroll
            for (int e = 0; e < 4; e++) sacc[i][e] = 0.0f;
#pragma unroll
        for (int kt = 0; kt < 8; kt++) {
            uint32_t qh[4], ql[4], kh[4];
            ldm4(qh, base + AQH_O + lmQ + kt * 32);
            ldm4(ql, base + AQL_O + lmQ + kt * 32);
            ldm4(kh, sg + lmK + kt * 32);
#pragma unroll
            for (int nt = 0; nt < 2; nt++) {
                mma_f16(sacc[nt], qh, kh[nt], kh[nt + 2]);
                mma_f16(sacc[nt], ql, kh[nt], kh[nt + 2]);
            }
        }
        {
            int lim_lo = 3968 + l0 + r_lo;
            int lim_hi = lim_lo + 8;
#pragma unroll
            for (int nt = 0; nt < 2; nt++) {
                int c0 = 16 * wq + 8 * nt + (lane & 3) * 2;
                int k0g = s0 + c0;
                float v0 = (k0g     <= lim_lo) ? sacc[nt][0] : -1e30f;
                float v1 = (k0g + 1 <= lim_lo) ? sacc[nt][1] : -1e30f;
                float v2 = (k0g     <= lim_hi) ? sacc[nt][2] : -1e30f;
                float v3 = (k0g + 1 <= lim_hi) ? sacc[nt][3] : -1e30f;
                *(float2*)(sm + ASS_O + r_lo * PQB + c0 * 4) = make_float2(v0, v1);
                *(float2*)(sm + ASS_O + r_hi * PQB + c0 * 4) = make_float2(v2, v3);
            }
        }
        __syncthreads();

        // ---- parallel online softmax (8 threads/row); P single fp16 ----
        {
            int r = tid >> 3, cg = tid & 7;
            float* rowp = (float*)(sm + ASS_O + r * PQB);
            float4 a = ((float4*)rowp)[cg * 2];
            float4 b = ((float4*)rowp)[cg * 2 + 1];
            float mx = fmaxf(fmaxf(fmaxf(a.x, a.y), fmaxf(a.z, a.w)),
                             fmaxf(fmaxf(b.x, b.y), fmaxf(b.z, b.w)));
#pragma unroll
            for (int o = 1; o < 8; o <<= 1)
                mx = fmaxf(mx, __shfl_xor_sync(0xffffffffu, mx, o));
            float mOld = *(float*)(sm + ASM_O + r * 4);
            mx = fmaxf(mx, mOld);
            float e[8];
            e[0] = __expf(a.x - mx); e[1] = __expf(a.y - mx);
            e[2] = __expf(a.z - mx); e[3] = __expf(a.w - mx);
            e[4] = __expf(b.x - mx); e[5] = __expf(b.y - mx);
            e[6] = __expf(b.z - mx); e[7] = __expf(b.w - mx);
            float s = ((e[0] + e[1]) + (e[2] + e[3])) +
                      ((e[4] + e[5]) + (e[6] + e[7]));
#pragma unroll
            for (int o = 1; o < 8; o <<= 1)
                s += __shfl_xor_sync(0xffffffffu, s, o);
            uint32_t* ph = (uint32_t*)(sm + APH_O + r * PPB) + cg * 4;
#pragma unroll
            for (int j = 0; j < 4; j++) {
                __half2 p = __floats2half2_rn(e[2 * j], e[2 * j + 1]);
                ph[j] = *(uint32_t*)&p;
            }
            if (cg == 0) {
                float c = __expf(mOld - mx);
                *(float*)(sm + ASM_O + r * 4) = mx;
                *(float*)(sm + ASL_O + r * 4) =
                    *(float*)(sm + ASL_O + r * 4) * c + s;
                *(float*)(sm + ASC_O + r * 4) = c;
            }
        }
        __syncthreads();

        // ---- PV: O += P * V  (1 mma per oacc per kt) ----
        {
            float c_lo = *(float*)(sm + ASC_O + r_lo * 4);
            float c_hi = *(float*)(sm + ASC_O + r_hi * 4);
#pragma unroll
            for (int nt = 0; nt < 4; nt++) {
                oacc[nt][0] *= c_lo; oacc[nt][1] *= c_lo;
                oacc[nt][2] *= c_hi; oacc[nt][3] *= c_hi;
            }
        }
        const uint32_t vg = sg + 17408u;
#pragma unroll
        for (int kt = 0; kt < 4; kt++) {
            uint32_t p4[4];
            ldm4(p4, base + APH_O + lmP + kt * 32);
            uint32_t vrow = (uint32_t)(16 * kt) * PQB + lmV;
            uint32_t vh[4];
            ldm4t(vh, vg + vrow);
            mma_f16(oacc[0], p4, vh[0], vh[1]);
            mma_f16(oacc[1], p4, vh[2], vh[3]);
            ldm4t(vh, vg + vrow + 32);
            mma_f16(oacc[2], p4, vh[0], vh[1]);
            mma_f16(oacc[3], p4, vh[2], vh[3]);
        }
    }

    float* oBase = pO + ((size_t)(z * HQ + h) * LQ) * DH;
#pragma unroll
    for (int nt = 0; nt < 4; nt++) {
        int d = 32 * wq + 8 * nt + (lane & 3) * 2;
        *(float2*)(oBase + (size_t)(l0 + r_lo) * DH + d) =
            make_float2(oacc[nt][0], oacc[nt][1]);
        *(float2*)(oBase + (size_t)(l0 + r_hi) * DH + d) =
            make_float2(oacc[nt][2], oacc[nt][3]);
    }
    if (tid < 32) {
        size_t mi = (size_t)(z * HQ + h) * LQ + l0 + tid;
        pM[mi] = *(float*)(sm + ASM_O + tid * 4);
        pL[mi] = *(float*)(sm + ASL_O + tid * 4);
    }
}

// ---- combine the two kv-splits -> g_o ----
__global__ __launch_bounds__(128) void attn_combine(
    const float* __restrict__ pO, const float* __restrict__ pM,
    const float* __restrict__ pL)
{
    int h = blockIdx.x, l = blockIdx.y, d = threadIdx.x;
    size_t i0 = (size_t)h * LQ + l;
    size_t i1 = (size_t)(HQ + h) * LQ + l;
    float m0 = pM[i0], m1 = pM[i1];
    float l0v = pL[i0], l1v = pL[i1];
    float m = fmaxf(m0, m1);
    float e0 = __expf(m0 - m), e1 = __expf(m1 - m);
    float inv = 1.0f / (e0 * l0v + e1 * l1v);
    float o0 = pO[(i0 * DH) + d];
    float o1 = pO[(i1 * DH) + d];
    g_o[(size_t)l * HID + h * DH + d] = (e0 * o0 + e1 * o1) * inv;
}

// ---------------- launch ----------------
extern "C" void kernel_launch(void* const* d_in, const int* in_sizes, int n_in,
                              void* d_out, int out_size) {
    const float* x     = (const float*)d_in[0];
    const float* xctx  = (const float*)d_in[1];
    const float* cosq  = (const float*)d_in[2];
    const float* sinq  = (const float*)d_in[3];
    const float* cosk  = (const float*)d_in[4];
    const float* sink  = (const float*)d_in[5];
    const float* cK    = (const float*)d_in[6];
    const float* cV    = (const float*)d_in[7];
    const float* Wq    = (const float*)d_in[9];
    const float* Wk    = (const float*)d_in[10];
    const float* Wv    = (const float*)d_in[11];
    const float* Wo    = (const float*)d_in[12];
    const float* qw    = (const float*)d_in[13];
    const float* kw    = (const float*)d_in[14];

    float* out  = (float*)d_out;
    float* kOut = out + (size_t)LQ * HID;
    float* vOut = kOut + (size_t)HKV * TT * DH;

    cudaFuncSetAttribute(gemm_f16, cudaFuncAttributeMaxDynamicSharedMemorySize,
                         61440);
    cudaFuncSetAttribute(attn_mma, cudaFuncAttributeMaxDynamicSharedMemorySize,
                         ATTN_SMEM);

    __half *actH, *actL, *wq, *wk, *wv, *wo, *goH, *goL, *qrH, *qrL, *kc, *vc;
    cudaGetSymbolAddress((void**)&actH, c_actH);
    cudaGetSymbolAddress((void**)&actL, c_actL);
    cudaGetSymbolAddress((void**)&wq,   c_wq);
    cudaGetSymbolAddress((void**)&wk,   c_wk);
    cudaGetSymbolAddress((void**)&wv,   c_wv);
    cudaGetSymbolAddress((void**)&wo,   c_wo);
    cudaGetSymbolAddress((void**)&goH,  c_goH);
    cudaGetSymbolAddress((void**)&goL,  c_goL);
    cudaGetSymbolAddress((void**)&qrH,  c_qrH);
    cudaGetSymbolAddress((void**)&qrL,  c_qrL);
    cudaGetSymbolAddress((void**)&kc,   c_kc);
    cudaGetSymbolAddress((void**)&vc,   c_vc);
    float *gq, *go, *gk, *gv, *aO, *aM, *aL;
    cudaGetSymbolAddress((void**)&gq, g_q);
    cudaGetSymbolAddress((void**)&go, g_o);
    cudaGetSymbolAddress((void**)&gk, g_k);
    cudaGetSymbolAddress((void**)&gv, g_v);
    cudaGetSymbolAddress((void**)&aO, g_aO);
    cudaGetSymbolAddress((void**)&aM, g_aM);
    cudaGetSymbolAddress((void**)&aL, g_aL);

    cache_split<<<(2 * CCH4 + 255) / 256, 256>>>(
        (const float4*)cK, (const float4*)cV, (uint2*)kc, (uint2*)vc);
    cvt_a<<<(ACT4 + 255) / 256, 256>>>((const float4*)xctx, (const float4*)x,
                                       (uint2*)actH, (uint2*)actL);
    {
        long long tot = 2LL * WQ4 + 2LL * WK4;
        cvt_w<<<(unsigned)((tot + 255) / 256), 256>>>(
            (const float4*)Wq, (const float4*)Wk, (const float4*)Wv,
            (const float4*)Wo,
            (uint2*)wq, (uint2*)wk, (uint2*)wv, (uint2*)wo);
    }
    // q projection: split-K=2 -> partials g_k/g_v -> add -> g_q
    gemm_f16<<<dim3(64, 2, 2), 256, 61440>>>(
        actH + (size_t)CTXN * HID, actL + (size_t)CTXN * HID,
        wq, wq, gk, gv, HID, 2048);
    add_k<<<(LQ * HID / 4 + 255) / 256, 256>>>(
        (const float4*)gk, (const float4*)gv, (float4*)gq, LQ * HID / 4);
    // k/v projection (overwrites g_k/g_v)
    gemm_f16<<<dim3(16, 16, 2), 256, 61440>>>(
        actH, actL, wk, wv, gk, gv, HKV * DH, 0);
    qnorm_k<<<dim3(HQ, LQ), 128>>>(cosq, sinq, qw, qrH, qrL);
    kvnorm_k<<<dim3(HKV, TT), 128>>>(cosk, sink, kw, kOut, vOut, kc, vc);
    // attention: split-KV=2 + combine
    attn_mma<<<dim3(HQ, 4, 2), 256, ATTN_SMEM>>>(qrH, qrL, kc, vc, aO, aM, aL);
    attn_combine<<<dim3(HQ, LQ), 128>>>(aO, aM, aL);
    // output projection: split-K=2 -> partials -> add -> out
    cvt_go<<<(LQ * HID / 4 + 255) / 256, 256>>>((const float4*)go,
                                                (uint2*)goH, (uint2*)goL,
                                                LQ * HID / 4);
    gemm_f16<<<dim3(64, 2, 2), 256, 61440>>>(
        goH, goL, wo, wo, gk, gv, HID, 2048);
    add_k<<<(LQ * HID / 4 + 255) / 256, 256>>>(
        (const float4*)gk, (const float4*)gv, (float4*)out, LQ * HID / 4);
}